// round 2
// baseline (speedup 1.0000x reference)
#include <cuda_runtime.h>
#include <math.h>

#define B 4
#define N 2048
#define D 1024
#define H 64
#define BN (B*N)            // 8192
#define SCALE 0.125f        // H^-0.5
#define NBLK (N/64)         // 32
#define NPAIR (NBLK*(NBLK+1)/2)  // 528
#define NCHUNK 8            // j-block chunks of 4 for AV split

// ---- scratch (device globals; no allocations allowed) ----
__device__ float g_q[BN*H];
__device__ float g_k[BN*H];
__device__ float g_v[BN*H];
__device__ float g_S[(size_t)B*N*N];      // raw scores, upper triangle valid
__device__ float g_m[BN];
__device__ float g_linv[BN];
__device__ float g_part[NCHUNK*BN*H];

// ============================================================
// Kernel 1: QKV projection.  out = x @ W + b
// block: 128 rows x 64 cols, one of {q,k,v} per blockIdx.y
// ============================================================
__global__ __launch_bounds__(256) void qkv_kernel(
    const float* __restrict__ x,
    const float* __restrict__ Wq, const float* __restrict__ bq,
    const float* __restrict__ Wk, const float* __restrict__ bk,
    const float* __restrict__ Wv, const float* __restrict__ bv)
{
    __shared__ float Xs[128][36];   // BK=32, padded stride 36 (16B-aligned rows)
    __shared__ float Ws[32][64];

    const int which = blockIdx.y;
    const float* __restrict__ W    = (which == 0) ? Wq : (which == 1) ? Wk : Wv;
    const float* __restrict__ bias = (which == 0) ? bq : (which == 1) ? bk : bv;
    float* __restrict__ out        = (which == 0) ? g_q : (which == 1) ? g_k : g_v;

    const int row0 = blockIdx.x * 128;
    const int tid = threadIdx.x;
    const int tx = tid & 15, ty = tid >> 4;

    float acc[8][4] = {};

    for (int k0 = 0; k0 < D; k0 += 32) {
        // load X tile 128x32 (4 float4/thread)
        #pragma unroll
        for (int r = 0; r < 4; r++) {
            int row = r * 32 + (tid >> 3);
            int v4  = tid & 7;
            float4 t = *(const float4*)&x[(size_t)(row0 + row) * D + k0 + v4 * 4];
            *(float4*)&Xs[row][v4 * 4] = t;
        }
        // load W tile 32x64 (2 float4/thread)
        #pragma unroll
        for (int r = 0; r < 2; r++) {
            int idx = tid + r * 256;            // 0..511
            int wr = idx >> 4, c4 = idx & 15;
            float4 t = *(const float4*)&W[(size_t)(k0 + wr) * H + c4 * 4];
            *(float4*)&Ws[wr][c4 * 4] = t;
        }
        __syncthreads();

        #pragma unroll
        for (int kk = 0; kk < 32; kk++) {
            float a[8], bb[4];
            #pragma unroll
            for (int r = 0; r < 8; r++) a[r] = Xs[ty * 8 + r][kk];
            #pragma unroll
            for (int c = 0; c < 4; c++) bb[c] = Ws[kk][tx * 4 + c];
            #pragma unroll
            for (int r = 0; r < 8; r++)
                #pragma unroll
                for (int c = 0; c < 4; c++)
                    acc[r][c] += a[r] * bb[c];
        }
        __syncthreads();
    }

    #pragma unroll
    for (int r = 0; r < 8; r++) {
        int row = row0 + ty * 8 + r;
        #pragma unroll
        for (int c = 0; c < 4; c++) {
            int col = tx * 4 + c;
            out[row * H + col] = acc[r][c] + bias[col];
        }
    }
}

// ============================================================
// Kernel 2: S[b,i,j] = q_i . k_j  for upper-triangle 64x64 blocks only
// grid: (528 pairs, B)
// ============================================================
__global__ __launch_bounds__(256) void s_kernel()
{
    int p = blockIdx.x;
    int bi = 0;
    while (p >= NBLK - bi) { p -= NBLK - bi; bi++; }
    int bj = bi + p;
    int b = blockIdx.y;

    __shared__ float Qs[64][65];
    __shared__ float Ks[64][65];

    const float* __restrict__ q = g_q + ((size_t)b * N + bi * 64) * H;
    const float* __restrict__ k = g_k + ((size_t)b * N + bj * 64) * H;

    int tid = threadIdx.x;
    int tx = tid & 15, ty = tid >> 4;

    // load 64x64 tiles (scalar smem stores, float4 gmem loads)
    #pragma unroll
    for (int r = 0; r < 4; r++) {
        int idx = tid + r * 256;         // 0..1023
        int row = idx >> 4, c4 = idx & 15;
        float4 tq = *(const float4*)&q[row * H + c4 * 4];
        float4 tk = *(const float4*)&k[row * H + c4 * 4];
        Qs[row][c4*4+0]=tq.x; Qs[row][c4*4+1]=tq.y; Qs[row][c4*4+2]=tq.z; Qs[row][c4*4+3]=tq.w;
        Ks[row][c4*4+0]=tk.x; Ks[row][c4*4+1]=tk.y; Ks[row][c4*4+2]=tk.z; Ks[row][c4*4+3]=tk.w;
    }
    __syncthreads();

    float acc[4][4] = {};
    #pragma unroll
    for (int h = 0; h < 64; h++) {
        float a[4], bb[4];
        #pragma unroll
        for (int r = 0; r < 4; r++) a[r]  = Qs[ty * 4 + r][h];
        #pragma unroll
        for (int c = 0; c < 4; c++) bb[c] = Ks[tx * 4 + c][h];
        #pragma unroll
        for (int r = 0; r < 4; r++)
            #pragma unroll
            for (int c = 0; c < 4; c++)
                acc[r][c] += a[r] * bb[c];
    }

    #pragma unroll
    for (int r = 0; r < 4; r++) {
        int i = bi * 64 + ty * 4 + r;
        #pragma unroll
        for (int c = 0; c < 4; c++) {
            int j = bj * 64 + tx * 4 + c;
            g_S[((size_t)b * N + i) * N + j] = acc[r][c];
        }
    }
}

// ============================================================
// Kernel 3: per-row softmax stats over j in [i, N), skipping s==0
// grid: BN blocks x 256 threads
// ============================================================
__global__ __launch_bounds__(256) void stats_kernel()
{
    int row = blockIdx.x;           // b*N + i
    int i = row & (N - 1);
    const float* __restrict__ base = g_S + (size_t)row * N;
    int tid = threadIdx.x;

    float m = -INFINITY, l = 0.0f;
    for (int j = i + tid; j < N; j += 256) {
        float s = base[j];
        if (s != 0.0f) {                    // torch quirk: exact zeros -> -inf
            float t = s * SCALE;
            if (t > m) { l *= __expf(m - t); m = t; }
            l += __expf(t - m);
        }
    }

    __shared__ float sm[256], sl[256];
    sm[tid] = m; sl[tid] = l;
    __syncthreads();
    for (int o = 128; o > 0; o >>= 1) {
        if (tid < o) {
            float m1 = sm[tid], l1 = sl[tid];
            float m2 = sm[tid + o], l2 = sl[tid + o];
            float mm = fmaxf(m1, m2);
            float w1 = (m1 == mm) ? 1.0f : __expf(m1 - mm);
            float w2 = (m2 == mm) ? 1.0f : __expf(m2 - mm);
            sm[tid] = mm;
            sl[tid] = l1 * w1 + l2 * w2;
        }
        __syncthreads();
    }
    if (tid == 0) {
        g_m[row] = sm[0];
        g_linv[row] = 1.0f / sl[0];
    }
}

// ============================================================
// Kernel 4: out_partial[i,h] = sum_{j in chunk} P[j,i] * v[j,h]
// P[j,i] = (i>=j && S[j,i]!=0) ? exp(S[j,i]*SCALE - m_j)/l_j : 0
// grid: (NBLK, NCHUNK, B); each chunk covers 4 j-blocks
// ============================================================
__global__ __launch_bounds__(256) void av_kernel()
{
    int bi = blockIdx.x, chunk = blockIdx.y, b = blockIdx.z;
    int jb0 = chunk * 4;
    if (jb0 > bi) return;
    int jb1 = min(jb0 + 4, bi + 1);

    __shared__ float Ps[64][68];
    __shared__ float Vs[64][68];

    int tid = threadIdx.x;
    int tx = tid & 15, ty = tid >> 4;
    int i0 = bi * 64;

    float acc[4][4] = {};

    for (int jb = jb0; jb < jb1; jb++) {
        int j0 = jb * 64;
        __syncthreads();   // protect previous-iteration smem reads
        #pragma unroll
        for (int r = 0; r < 4; r++) {
            int idx = tid + r * 256;
            int row = idx >> 4, c4 = idx & 15;
            int j = j0 + row;
            float4 t = *(const float4*)&g_S[((size_t)b * N + j) * N + i0 + c4 * 4];
            float mj = g_m[b * N + j];
            float lj = g_linv[b * N + j];
            float pv[4] = {t.x, t.y, t.z, t.w};
            #pragma unroll
            for (int u = 0; u < 4; u++) {
                int i = i0 + c4 * 4 + u;
                bool valid = (j <= i) && (pv[u] != 0.0f);
                pv[u] = valid ? __expf(pv[u] * SCALE - mj) * lj : 0.0f;
            }
            Ps[row][c4*4+0]=pv[0]; Ps[row][c4*4+1]=pv[1];
            Ps[row][c4*4+2]=pv[2]; Ps[row][c4*4+3]=pv[3];
            float4 tv = *(const float4*)&g_v[((size_t)b * N + j) * H + c4 * 4];
            *(float4*)&Vs[row][c4 * 4] = tv;
        }
        __syncthreads();

        #pragma unroll
        for (int j = 0; j < 64; j++) {
            float4 av = *(const float4*)&Ps[j][ty * 4];
            float4 bv = *(const float4*)&Vs[j][tx * 4];
            float a[4] = {av.x, av.y, av.z, av.w};
            float bb[4] = {bv.x, bv.y, bv.z, bv.w};
            #pragma unroll
            for (int r = 0; r < 4; r++)
                #pragma unroll
                for (int c = 0; c < 4; c++)
                    acc[r][c] += a[r] * bb[c];
        }
    }

    #pragma unroll
    for (int r = 0; r < 4; r++) {
        int i = i0 + ty * 4 + r;
        #pragma unroll
        for (int c = 0; c < 4; c++) {
            g_part[((size_t)chunk * BN + b * N + i) * H + tx * 4 + c] = acc[r][c];
        }
    }
}

// ============================================================
// Kernel 5: reduce partial chunks into the output
// ============================================================
__global__ __launch_bounds__(256) void reduce_kernel(float* __restrict__ out)
{
    int idx = blockIdx.x * 256 + threadIdx.x;   // over BN*H
    if (idx >= BN * H) return;
    int row = idx / H;            // b*N + i
    int i = row & (N - 1);
    int nch = (i >> 6) / 4 + 1;   // valid chunks for this i-block
    float s = 0.0f;
    for (int c = 0; c < nch; c++)
        s += g_part[(size_t)c * BN * H + idx];
    out[idx] = s;
}

// ============================================================
extern "C" void kernel_launch(void* const* d_in, const int* in_sizes, int n_in,
                              void* d_out, int out_size)
{
    const float* x  = (const float*)d_in[0];
    const float* Wq = (const float*)d_in[1];
    const float* bq = (const float*)d_in[2];
    const float* Wk = (const float*)d_in[3];
    const float* bk = (const float*)d_in[4];
    const float* Wv = (const float*)d_in[5];
    const float* bv = (const float*)d_in[6];
    float* out = (float*)d_out;

    qkv_kernel<<<dim3(BN / 128, 3), 256>>>(x, Wq, bq, Wk, bk, Wv, bv);
    s_kernel<<<dim3(NPAIR, B), 256>>>();
    stats_kernel<<<BN, 256>>>();
    av_kernel<<<dim3(NBLK, NCHUNK, B), 256>>>();
    reduce_kernel<<<(BN * H + 255) / 256, 256>>>(out);
}

// round 8
// speedup vs baseline: 1.7176x; 1.7176x over previous
#include <cuda_runtime.h>
#include <cuda_bf16.h>
#include <math.h>
#include <stdint.h>

#define B 4
#define N 2048
#define D 1024
#define H 64
#define BN (B*N)            // 8192
#define SCALE 0.125f        // H^-0.5
#define NB2 16              // N/128
#define NPAIR2 (NB2*(NB2+1)/2)   // 136
#define NCHUNK 8

// ---- scratch (device globals) ----
__device__ __nv_bfloat16 g_xhi[BN*D];
__device__ __nv_bfloat16 g_xlo[BN*D];
__device__ __nv_bfloat16 g_bthi[3*H*D];   // [which][n][k] transposed weights
__device__ __nv_bfloat16 g_btlo[3*H*D];
__device__ __nv_bfloat16 g_qkhi[2*BN*H];  // q,k bf16 hi ([row][64])
__device__ __nv_bfloat16 g_qklo[2*BN*H];  // q,k bf16 lo
__device__ float g_v[BN*H];
__device__ float g_S[(size_t)B*N*N];
__device__ float g_m[BN];
__device__ float g_linv[BN];
__device__ float g_part[(size_t)NCHUNK*BN*H];

// ============================================================
// helpers
// ============================================================
__device__ __forceinline__ uint32_t smem_u32(const void* p) {
    uint32_t a;
    asm("{ .reg .u64 t; cvta.to.shared.u64 t, %1; cvt.u32.u64 %0, t; }" : "=r"(a) : "l"(p));
    return a;
}
static __device__ __forceinline__ uint32_t swz128(uint32_t off) { return off ^ ((off >> 3) & 0x70); }

__device__ __forceinline__ void ldsm_x4(uint32_t addr, uint32_t& r0, uint32_t& r1, uint32_t& r2, uint32_t& r3) {
    asm volatile("ldmatrix.sync.aligned.m8n8.x4.shared.b16 {%0,%1,%2,%3}, [%4];"
                 : "=r"(r0), "=r"(r1), "=r"(r2), "=r"(r3) : "r"(addr));
}
__device__ __forceinline__ void mma_bf16(float* c, uint32_t a0, uint32_t a1, uint32_t a2, uint32_t a3,
                                         uint32_t b0, uint32_t b1) {
    asm volatile("mma.sync.aligned.m16n8k16.row.col.f32.bf16.bf16.f32 "
                 "{%0,%1,%2,%3}, {%4,%5,%6,%7}, {%8,%9}, {%0,%1,%2,%3};"
                 : "+f"(c[0]), "+f"(c[1]), "+f"(c[2]), "+f"(c[3])
                 : "r"(a0), "r"(a1), "r"(a2), "r"(a3), "r"(b0), "r"(b1));
}
#define CP_ASYNC16(dst, src) asm volatile("cp.async.cg.shared.global [%0], [%1], 16;" :: "r"(dst), "l"(src))
#define CP_COMMIT() asm volatile("cp.async.commit_group;" ::: "memory")
#define CP_WAIT1() asm volatile("cp.async.wait_group 1;" ::: "memory")
#define CP_WAIT0() asm volatile("cp.async.wait_group 0;" ::: "memory")

// ============================================================
// Kernel 0a: split x into bf16 hi/lo
// ============================================================
__global__ __launch_bounds__(256) void convert_x_kernel(const float* __restrict__ x)
{
    size_t idx = ((size_t)blockIdx.x * 256 + threadIdx.x) * 4;
    float4 v = *(const float4*)&x[idx];
    float f[4] = {v.x, v.y, v.z, v.w};
    __nv_bfloat16 hi[4], lo[4];
    #pragma unroll
    for (int u = 0; u < 4; u++) {
        hi[u] = __float2bfloat16(f[u]);
        lo[u] = __float2bfloat16(f[u] - __bfloat162float(hi[u]));
    }
    *(__nv_bfloat162*)&g_xhi[idx]     = __nv_bfloat162(hi[0], hi[1]);
    *(__nv_bfloat162*)&g_xhi[idx + 2] = __nv_bfloat162(hi[2], hi[3]);
    *(__nv_bfloat162*)&g_xlo[idx]     = __nv_bfloat162(lo[0], lo[1]);
    *(__nv_bfloat162*)&g_xlo[idx + 2] = __nv_bfloat162(lo[2], lo[3]);
}

// ============================================================
// Kernel 0b: transpose+split W -> [which][n][k]
// ============================================================
__global__ __launch_bounds__(256) void convert_w_kernel(
    const float* __restrict__ Wq, const float* __restrict__ Wk, const float* __restrict__ Wv)
{
    int n = blockIdx.x;          // 0..63
    int which = blockIdx.y;      // 0..2
    const float* __restrict__ W = (which == 0) ? Wq : (which == 1) ? Wk : Wv;
    int base = which * H * D + n * D;
    for (int it = 0; it < 4; it++) {
        int k = threadIdx.x + it * 256;
        float w = W[(size_t)k * H + n];
        __nv_bfloat16 hi = __float2bfloat16(w);
        __nv_bfloat16 lo = __float2bfloat16(w - __bfloat162float(hi));
        g_bthi[base + k] = hi;
        g_btlo[base + k] = lo;
    }
}

// ============================================================
// Kernel 1: QKV via mma.sync bf16 hi/lo (3 phases, 48 K64-chunks).
// CTA 128x64, 8 warps (4 M x 2 N), warp tile 32x32.
// smem: A[2][128][128B] (32KB) + Bt[2][64][128B] (16KB) = 48KB, cp.async pipelined.
// ============================================================
__global__ __launch_bounds__(256) void qkv_mma_kernel(
    const float* __restrict__ bq, const float* __restrict__ bk, const float* __restrict__ bv)
{
    __shared__ char sm[49152];
    const uint32_t smA = smem_u32(sm);
    const uint32_t smB = smA + 32768;

    const int tid = threadIdx.x;
    const int w = tid >> 5, l = tid & 31;
    const int wm = w & 3, wn = w >> 2;
    const int row0 = blockIdx.x * 128;
    const int which = blockIdx.y;

    const __nv_bfloat16* __restrict__ bt_hi = g_bthi + which * (H * D);
    const __nv_bfloat16* __restrict__ bt_lo = g_btlo + which * (H * D);

    float acc[2][4][4] = {};

    // async load of chunk c into buffer buf
    auto issue_load = [&](int c, int buf) {
        const int phase = c >> 4;
        const int k0 = (c & 15) * 64;
        const __nv_bfloat16* __restrict__ Asrc = (phase == 1) ? g_xlo : g_xhi;
        const __nv_bfloat16* __restrict__ Bsrc = (phase == 2) ? bt_lo : bt_hi;
        #pragma unroll
        for (int it = 0; it < 4; it++) {
            int lin = tid + it * 256;          // 0..1023
            int r = lin >> 3, c16 = lin & 7;
            uint32_t dst = smA + buf * 16384 + swz128(r * 128 + c16 * 16);
            CP_ASYNC16(dst, Asrc + (size_t)(row0 + r) * D + k0 + c16 * 8);
        }
        #pragma unroll
        for (int it = 0; it < 2; it++) {
            int lin = tid + it * 256;          // 0..511
            int r = lin >> 3, c16 = lin & 7;
            uint32_t dst = smB + buf * 8192 + swz128(r * 128 + c16 * 16);
            CP_ASYNC16(dst, Bsrc + (size_t)r * D + k0 + c16 * 8);
        }
    };

    issue_load(0, 0);
    CP_COMMIT();

    for (int c = 0; c < 48; c++) {
        const int buf = c & 1;
        if (c < 47) { issue_load(c + 1, (c + 1) & 1); CP_COMMIT(); CP_WAIT1(); }
        else        { CP_WAIT0(); }
        __syncthreads();

        const uint32_t baseA = smA + buf * 16384;
        const uint32_t baseB = smB + buf * 8192;
        #pragma unroll
        for (int ks = 0; ks < 4; ks++) {
            const int kb = ks * 32;
            uint32_t a[2][4];
            #pragma unroll
            for (int t = 0; t < 2; t++) {
                int row = wm * 32 + t * 16 + (l & 7) + (l & 8);
                uint32_t addr = baseA + swz128(row * 128 + kb + (l & 16));
                ldsm_x4(addr, a[t][0], a[t][1], a[t][2], a[t][3]);
            }
            uint32_t bfr[2][4];
            #pragma unroll
            for (int bp = 0; bp < 2; bp++) {
                int n = wn * 32 + bp * 16 + ((l & 16) >> 1) + (l & 7);
                uint32_t addr = baseB + swz128(n * 128 + kb + ((l & 8) << 1));
                ldsm_x4(addr, bfr[bp][0], bfr[bp][1], bfr[bp][2], bfr[bp][3]);
            }
            #pragma unroll
            for (int t = 0; t < 2; t++)
                #pragma unroll
                for (int u = 0; u < 4; u++)
                    mma_bf16(acc[t][u], a[t][0], a[t][1], a[t][2], a[t][3],
                             bfr[u >> 1][(u & 1) * 2], bfr[u >> 1][(u & 1) * 2 + 1]);
        }
        __syncthreads();
    }

    // epilogue
    const float* __restrict__ bias = (which == 0) ? bq : (which == 1) ? bk : bv;
    const int l4 = l >> 2, l2 = 2 * (l & 3);
    #pragma unroll
    for (int t = 0; t < 2; t++) {
        #pragma unroll
        for (int u = 0; u < 4; u++) {
            int r = row0 + wm * 32 + t * 16 + l4;
            int col = wn * 32 + u * 8 + l2;
            float b0 = bias[col], b1 = bias[col + 1];
            float v0 = acc[t][u][0] + b0, v1 = acc[t][u][1] + b1;
            float v2 = acc[t][u][2] + b0, v3 = acc[t][u][3] + b1;
            if (which == 2) {
                float2 p0 = {v0, v1}, p1 = {v2, v3};
                *(float2*)&g_v[(size_t)r * H + col] = p0;
                *(float2*)&g_v[(size_t)(r + 8) * H + col] = p1;
            } else {
                size_t off = (size_t)which * BN * H;
                __nv_bfloat16 h0 = __float2bfloat16(v0), h1 = __float2bfloat16(v1);
                __nv_bfloat16 h2 = __float2bfloat16(v2), h3 = __float2bfloat16(v3);
                *(__nv_bfloat162*)&g_qkhi[off + (size_t)r * H + col] = __nv_bfloat162(h0, h1);
                *(__nv_bfloat162*)&g_qkhi[off + (size_t)(r + 8) * H + col] = __nv_bfloat162(h2, h3);
                __nv_bfloat162 lo0(__float2bfloat16(v0 - __bfloat162float(h0)),
                                   __float2bfloat16(v1 - __bfloat162float(h1)));
                __nv_bfloat162 lo1(__float2bfloat16(v2 - __bfloat162float(h2)),
                                   __float2bfloat16(v3 - __bfloat162float(h3)));
                *(__nv_bfloat162*)&g_qklo[off + (size_t)r * H + col] = lo0;
                *(__nv_bfloat162*)&g_qklo[off + (size_t)(r + 8) * H + col] = lo1;
            }
        }
    }
}

// ============================================================
// Kernel 2: S = Q.K^T via mma.sync bf16 hi/lo, 128x128 triangular tiles.
// 8 warps (4 M x 2 N), warp tile 32x64. Dynamic smem 64KB:
// Qhi@0, Qlo@16K, Khi@32K, Klo@48K — each [128][128B] swizzled.
// ============================================================
__global__ __launch_bounds__(256) void s_mma_kernel()
{
    extern __shared__ char sms[];
    const uint32_t smb = smem_u32(sms);

    int p = blockIdx.x;
    int bi = 0;
    while (p >= NB2 - bi) { p -= NB2 - bi; bi++; }
    int bj = bi + p;
    int b = blockIdx.y;

    const int tid = threadIdx.x;
    const int w = tid >> 5, l = tid & 31;
    const int wm = w & 3, wn = w >> 2;

    const __nv_bfloat16* __restrict__ src[4] = {
        g_qkhi + (size_t)(b * N + bi * 128) * H,
        g_qklo + (size_t)(b * N + bi * 128) * H,
        g_qkhi + (size_t)BN * H + (size_t)(b * N + bj * 128) * H,
        g_qklo + (size_t)BN * H + (size_t)(b * N + bj * 128) * H
    };
    #pragma unroll
    for (int tile = 0; tile < 4; tile++) {
        #pragma unroll
        for (int it = 0; it < 4; it++) {
            int lin = tid + it * 256;          // 0..1023
            int r = lin >> 3, c16 = lin & 7;
            uint4 v = *(const uint4*)(src[tile] + (size_t)r * H + c16 * 8);
            *(uint4*)(sms + tile * 16384 + swz128(r * 128 + c16 * 16)) = v;
        }
    }
    __syncthreads();

    float acc[2][8][4] = {};
    #pragma unroll
    for (int pass = 0; pass < 3; pass++) {
        const uint32_t aBase = smb + ((pass == 1) ? 16384 : 0);
        const uint32_t bBase = smb + ((pass == 2) ? 49152 : 32768);
        #pragma unroll
        for (int ks = 0; ks < 4; ks++) {
            const int kb = ks * 32;
            uint32_t a[2][4];
            #pragma unroll
            for (int t = 0; t < 2; t++) {
                int row = wm * 32 + t * 16 + (l & 7) + (l & 8);
                ldsm_x4(aBase + swz128(row * 128 + kb + (l & 16)), a[t][0], a[t][1], a[t][2], a[t][3]);
            }
            uint32_t bfr[4][4];
            #pragma unroll
            for (int bp = 0; bp < 4; bp++) {
                int n = wn * 64 + bp * 16 + ((l & 16) >> 1) + (l & 7);
                ldsm_x4(bBase + swz128(n * 128 + kb + ((l & 8) << 1)),
                        bfr[bp][0], bfr[bp][1], bfr[bp][2], bfr[bp][3]);
            }
            #pragma unroll
            for (int t = 0; t < 2; t++)
                #pragma unroll
                for (int u = 0; u < 8; u++)
                    mma_bf16(acc[t][u], a[t][0], a[t][1], a[t][2], a[t][3],
                             bfr[u >> 1][(u & 1) * 2], bfr[u >> 1][(u & 1) * 2 + 1]);
        }
    }

    const int l4 = l >> 2, l2 = 2 * (l & 3);
    #pragma unroll
    for (int t = 0; t < 2; t++) {
        #pragma unroll
        for (int u = 0; u < 8; u++) {
            int i = bi * 128 + wm * 32 + t * 16 + l4;
            int j = bj * 128 + wn * 64 + u * 8 + l2;
            float2 p0 = {acc[t][u][0], acc[t][u][1]};
            float2 p1 = {acc[t][u][2], acc[t][u][3]};
            *(float2*)&g_S[((size_t)(b * N + i)) * N + j] = p0;
            *(float2*)&g_S[((size_t)(b * N + i + 8)) * N + j] = p1;
        }
    }
}

// ============================================================
// Kernel 3: per-row softmax stats over j in [i, N), skipping s==0
// ============================================================
__global__ __launch_bounds__(256) void stats_kernel()
{
    int row = blockIdx.x;
    int i = row & (N - 1);
    const float* __restrict__ base = g_S + (size_t)row * N;
    int tid = threadIdx.x;

    float m = -INFINITY, l = 0.0f;
    for (int j = i + tid; j < N; j += 256) {
        float s = base[j];
        if (s != 0.0f) {
            float t = s * SCALE;
            if (t > m) { l *= __expf(m - t); m = t; }
            l += __expf(t - m);
        }
    }

    __shared__ float sm_[256], sl[256];
    sm_[tid] = m; sl[tid] = l;
    __syncthreads();
    for (int o = 128; o > 0; o >>= 1) {
        if (tid < o) {
            float m1 = sm_[tid], l1 = sl[tid];
            float m2 = sm_[tid + o], l2 = sl[tid + o];
            float mm = fmaxf(m1, m2);
            float w1 = (m1 == mm) ? 1.0f : __expf(m1 - mm);
            float w2 = (m2 == mm) ? 1.0f : __expf(m2 - mm);
            sm_[tid] = mm;
            sl[tid] = l1 * w1 + l2 * w2;
        }
        __syncthreads();
    }
    if (tid == 0) {
        g_m[row] = sm_[0];
        g_linv[row] = 1.0f / sl[0];
    }
}

// ============================================================
// Kernel 4: AV partials. i-tile 128, chunk = 4 j64-blocks.
// ============================================================
__global__ __launch_bounds__(256) void av_kernel()
{
    int p = blockIdx.x, b = blockIdx.y;
    int bi = 0;
    for (;;) {
        int nc = ((2 * bi + 1) >> 2) + 1;
        if (p < nc) break;
        p -= nc; bi++;
    }
    int chunk = p;
    int i0 = bi * 128;
    int jb0 = chunk * 4;
    int jb_end = min(jb0 + 4, 2 * bi + 2);

    __shared__ float Ps[64][128];
    __shared__ float Vs[64][64];

    int tid = threadIdx.x;
    int tx = tid & 15, ty = tid >> 4;

    float acc[8][4] = {};

    for (int jb = jb0; jb < jb_end; jb++) {
        int j0 = jb * 64;
        __syncthreads();
        #pragma unroll
        for (int r = 0; r < 8; r++) {
            int lin = tid + r * 256;
            int jr = lin >> 5, c4 = lin & 31;
            int j = j0 + jr;
            float4 t = *(const float4*)&g_S[((size_t)b * N + j) * N + i0 + c4 * 4];
            float mj = g_m[b * N + j];
            float lj = g_linv[b * N + j];
            float pv[4] = {t.x, t.y, t.z, t.w};
            #pragma unroll
            for (int u = 0; u < 4; u++) {
                int i = i0 + c4 * 4 + u;
                bool valid = (j <= i) && (pv[u] != 0.0f);
                pv[u] = valid ? __expf(pv[u] * SCALE - mj) * lj : 0.0f;
            }
            float4 o = {pv[0], pv[1], pv[2], pv[3]};
            *(float4*)&Ps[jr][c4 * 4] = o;
        }
        #pragma unroll
        for (int r = 0; r < 4; r++) {
            int lin = tid + r * 256;
            int jr = lin >> 4, c4 = lin & 15;
            float4 tv = *(const float4*)&g_v[((size_t)b * N + j0 + jr) * H + c4 * 4];
            *(float4*)&Vs[jr][c4 * 4] = tv;
        }
        __syncthreads();

        #pragma unroll 4
        for (int j = 0; j < 64; j++) {
            float4 a0 = *(const float4*)&Ps[j][ty * 8];
            float4 a1 = *(const float4*)&Ps[j][ty * 8 + 4];
            float4 bv = *(const float4*)&Vs[j][tx * 4];
            float a[8] = {a0.x, a0.y, a0.z, a0.w, a1.x, a1.y, a1.z, a1.w};
            float bb[4] = {bv.x, bv.y, bv.z, bv.w};
            #pragma unroll
            for (int r = 0; r < 8; r++)
                #pragma unroll
                for (int c = 0; c < 4; c++)
                    acc[r][c] += a[r] * bb[c];
        }
    }

    #pragma unroll
    for (int r = 0; r < 8; r++) {
        int i = i0 + ty * 8 + r;
        float4 o = {acc[r][0], acc[r][1], acc[r][2], acc[r][3]};
        *(float4*)&g_part[((size_t)chunk * BN + b * N + i) * H + tx * 4] = o;
    }
}

// ============================================================
// Kernel 5: reduce partial chunks
// ============================================================
__global__ __launch_bounds__(256) void reduce_kernel(float* __restrict__ out)
{
    int idx = blockIdx.x * 256 + threadIdx.x;
    if (idx >= BN * H) return;
    int row = idx / H;
    int i = row & (N - 1);
    int nch = (i >> 8) + 1;
    float s = 0.0f;
    for (int c = 0; c < nch; c++)
        s += g_part[(size_t)c * BN * H + idx];
    out[idx] = s;
}

// ============================================================
extern "C" void kernel_launch(void* const* d_in, const int* in_sizes, int n_in,
                              void* d_out, int out_size)
{
    const float* x  = (const float*)d_in[0];
    const float* Wq = (const float*)d_in[1];
    const float* bq = (const float*)d_in[2];
    const float* Wk = (const float*)d_in[3];
    const float* bk = (const float*)d_in[4];
    const float* Wv = (const float*)d_in[5];
    const float* bv = (const float*)d_in[6];
    float* out = (float*)d_out;

    cudaFuncSetAttribute(s_mma_kernel, cudaFuncAttributeMaxDynamicSharedMemorySize, 65536);

    convert_x_kernel<<<(BN * D) / 1024, 256>>>(x);
    convert_w_kernel<<<dim3(H, 3), 256>>>(Wq, Wk, Wv);
    qkv_mma_kernel<<<dim3(BN / 128, 3), 256>>>(bq, bk, bv);
    s_mma_kernel<<<dim3(NPAIR2, B), 256, 65536>>>();
    stats_kernel<<<BN, 256>>>();
    av_kernel<<<dim3(72, B), 256>>>();
    reduce_kernel<<<(BN * H + 255) / 256, 256>>>(out);
}

// round 9
// speedup vs baseline: 1.9782x; 1.1517x over previous
#include <cuda_runtime.h>
#include <cuda_bf16.h>
#include <cuda_fp16.h>
#include <math.h>
#include <stdint.h>

#define B 4
#define N 2048
#define D 1024
#define H 64
#define BN (B*N)            // 8192
#define SCALE 0.125f        // H^-0.5
#define NB2 16              // N/128
#define NPAIR2 (NB2*(NB2+1)/2)   // 136
#define NCHUNK 8

// ---- scratch (device globals) ----
__device__ __nv_bfloat16 g_xhi[BN*D];
__device__ __nv_bfloat16 g_xlo[BN*D];
__device__ __nv_bfloat16 g_bthi[3*H*D];   // [which][n][k] transposed weights
__device__ __nv_bfloat16 g_btlo[3*H*D];
__device__ __nv_bfloat16 g_qkhi[2*BN*H];  // q,k bf16 hi ([row][64])
__device__ __nv_bfloat16 g_qklo[2*BN*H];  // q,k bf16 lo
__device__ float g_v[BN*H];
__device__ float g_S[(size_t)B*N*N];
__device__ __half g_E[(size_t)B*N*N];     // unnormalized exp, fp16, [b][j][i]
__device__ float g_linv[BN];
__device__ __half g_vhi[BN*H];            // v * linv, fp16 hi
__device__ __half g_vlo[BN*H];            // residual
__device__ float g_part[(size_t)NCHUNK*BN*H];

// ============================================================
// helpers
// ============================================================
__device__ __forceinline__ uint32_t smem_u32(const void* p) {
    uint32_t a;
    asm("{ .reg .u64 t; cvta.to.shared.u64 t, %1; cvt.u32.u64 %0, t; }" : "=r"(a) : "l"(p));
    return a;
}
static __device__ __forceinline__ uint32_t swz128(uint32_t off) { return off ^ ((off >> 3) & 0x70); }

__device__ __forceinline__ void ldsm_x4(uint32_t addr, uint32_t& r0, uint32_t& r1, uint32_t& r2, uint32_t& r3) {
    asm volatile("ldmatrix.sync.aligned.m8n8.x4.shared.b16 {%0,%1,%2,%3}, [%4];"
                 : "=r"(r0), "=r"(r1), "=r"(r2), "=r"(r3) : "r"(addr));
}
__device__ __forceinline__ void ldsm_x4_t(uint32_t addr, uint32_t& r0, uint32_t& r1, uint32_t& r2, uint32_t& r3) {
    asm volatile("ldmatrix.sync.aligned.m8n8.x4.trans.shared.b16 {%0,%1,%2,%3}, [%4];"
                 : "=r"(r0), "=r"(r1), "=r"(r2), "=r"(r3) : "r"(addr));
}
__device__ __forceinline__ void mma_bf16(float* c, uint32_t a0, uint32_t a1, uint32_t a2, uint32_t a3,
                                         uint32_t b0, uint32_t b1) {
    asm volatile("mma.sync.aligned.m16n8k16.row.col.f32.bf16.bf16.f32 "
                 "{%0,%1,%2,%3}, {%4,%5,%6,%7}, {%8,%9}, {%0,%1,%2,%3};"
                 : "+f"(c[0]), "+f"(c[1]), "+f"(c[2]), "+f"(c[3])
                 : "r"(a0), "r"(a1), "r"(a2), "r"(a3), "r"(b0), "r"(b1));
}
__device__ __forceinline__ void mma_fp16(float* c, uint32_t a0, uint32_t a1, uint32_t a2, uint32_t a3,
                                         uint32_t b0, uint32_t b1) {
    asm volatile("mma.sync.aligned.m16n8k16.row.col.f32.f16.f16.f32 "
                 "{%0,%1,%2,%3}, {%4,%5,%6,%7}, {%8,%9}, {%0,%1,%2,%3};"
                 : "+f"(c[0]), "+f"(c[1]), "+f"(c[2]), "+f"(c[3])
                 : "r"(a0), "r"(a1), "r"(a2), "r"(a3), "r"(b0), "r"(b1));
}
#define CP_ASYNC16(dst, src) asm volatile("cp.async.cg.shared.global [%0], [%1], 16;" :: "r"(dst), "l"(src))
#define CP_COMMIT() asm volatile("cp.async.commit_group;" ::: "memory")
#define CP_WAIT1() asm volatile("cp.async.wait_group 1;" ::: "memory")
#define CP_WAIT0() asm volatile("cp.async.wait_group 0;" ::: "memory")

// ============================================================
// Kernel 0a: split x into bf16 hi/lo
// ============================================================
__global__ __launch_bounds__(256) void convert_x_kernel(const float* __restrict__ x)
{
    size_t idx = ((size_t)blockIdx.x * 256 + threadIdx.x) * 4;
    float4 v = *(const float4*)&x[idx];
    float f[4] = {v.x, v.y, v.z, v.w};
    __nv_bfloat16 hi[4], lo[4];
    #pragma unroll
    for (int u = 0; u < 4; u++) {
        hi[u] = __float2bfloat16(f[u]);
        lo[u] = __float2bfloat16(f[u] - __bfloat162float(hi[u]));
    }
    *(__nv_bfloat162*)&g_xhi[idx]     = __nv_bfloat162(hi[0], hi[1]);
    *(__nv_bfloat162*)&g_xhi[idx + 2] = __nv_bfloat162(hi[2], hi[3]);
    *(__nv_bfloat162*)&g_xlo[idx]     = __nv_bfloat162(lo[0], lo[1]);
    *(__nv_bfloat162*)&g_xlo[idx + 2] = __nv_bfloat162(lo[2], lo[3]);
}

// ============================================================
// Kernel 0b: transpose+split W -> [which][n][k]
// ============================================================
__global__ __launch_bounds__(256) void convert_w_kernel(
    const float* __restrict__ Wq, const float* __restrict__ Wk, const float* __restrict__ Wv)
{
    int n = blockIdx.x;
    int which = blockIdx.y;
    const float* __restrict__ W = (which == 0) ? Wq : (which == 1) ? Wk : Wv;
    int base = which * H * D + n * D;
    for (int it = 0; it < 4; it++) {
        int k = threadIdx.x + it * 256;
        float w = W[(size_t)k * H + n];
        __nv_bfloat16 hi = __float2bfloat16(w);
        __nv_bfloat16 lo = __float2bfloat16(w - __bfloat162float(hi));
        g_bthi[base + k] = hi;
        g_btlo[base + k] = lo;
    }
}

// ============================================================
// Kernel 1: QKV via mma.sync bf16 hi/lo (3 phases, 48 K64-chunks).
// ============================================================
__global__ __launch_bounds__(256) void qkv_mma_kernel(
    const float* __restrict__ bq, const float* __restrict__ bk, const float* __restrict__ bv)
{
    __shared__ char sm[49152];
    const uint32_t smA = smem_u32(sm);
    const uint32_t smB = smA + 32768;

    const int tid = threadIdx.x;
    const int w = tid >> 5, l = tid & 31;
    const int wm = w & 3, wn = w >> 2;
    const int row0 = blockIdx.x * 128;
    const int which = blockIdx.y;

    const __nv_bfloat16* __restrict__ bt_hi = g_bthi + which * (H * D);
    const __nv_bfloat16* __restrict__ bt_lo = g_btlo + which * (H * D);

    float acc[2][4][4] = {};

    auto issue_load = [&](int c, int buf) {
        const int phase = c >> 4;
        const int k0 = (c & 15) * 64;
        const __nv_bfloat16* __restrict__ Asrc = (phase == 1) ? g_xlo : g_xhi;
        const __nv_bfloat16* __restrict__ Bsrc = (phase == 2) ? bt_lo : bt_hi;
        #pragma unroll
        for (int it = 0; it < 4; it++) {
            int lin = tid + it * 256;
            int r = lin >> 3, c16 = lin & 7;
            uint32_t dst = smA + buf * 16384 + swz128(r * 128 + c16 * 16);
            CP_ASYNC16(dst, Asrc + (size_t)(row0 + r) * D + k0 + c16 * 8);
        }
        #pragma unroll
        for (int it = 0; it < 2; it++) {
            int lin = tid + it * 256;
            int r = lin >> 3, c16 = lin & 7;
            uint32_t dst = smB + buf * 8192 + swz128(r * 128 + c16 * 16);
            CP_ASYNC16(dst, Bsrc + (size_t)r * D + k0 + c16 * 8);
        }
    };

    issue_load(0, 0);
    CP_COMMIT();

    for (int c = 0; c < 48; c++) {
        const int buf = c & 1;
        if (c < 47) { issue_load(c + 1, (c + 1) & 1); CP_COMMIT(); CP_WAIT1(); }
        else        { CP_WAIT0(); }
        __syncthreads();

        const uint32_t baseA = smA + buf * 16384;
        const uint32_t baseB = smB + buf * 8192;
        #pragma unroll
        for (int ks = 0; ks < 4; ks++) {
            const int kb = ks * 32;
            uint32_t a[2][4];
            #pragma unroll
            for (int t = 0; t < 2; t++) {
                int row = wm * 32 + t * 16 + (l & 7) + (l & 8);
                uint32_t addr = baseA + swz128(row * 128 + kb + (l & 16));
                ldsm_x4(addr, a[t][0], a[t][1], a[t][2], a[t][3]);
            }
            uint32_t bfr[2][4];
            #pragma unroll
            for (int bp = 0; bp < 2; bp++) {
                int n = wn * 32 + bp * 16 + ((l & 16) >> 1) + (l & 7);
                uint32_t addr = baseB + swz128(n * 128 + kb + ((l & 8) << 1));
                ldsm_x4(addr, bfr[bp][0], bfr[bp][1], bfr[bp][2], bfr[bp][3]);
            }
            #pragma unroll
            for (int t = 0; t < 2; t++)
                #pragma unroll
                for (int u = 0; u < 4; u++)
                    mma_bf16(acc[t][u], a[t][0], a[t][1], a[t][2], a[t][3],
                             bfr[u >> 1][(u & 1) * 2], bfr[u >> 1][(u & 1) * 2 + 1]);
        }
        __syncthreads();
    }

    const float* __restrict__ bias = (which == 0) ? bq : (which == 1) ? bk : bv;
    const int l4 = l >> 2, l2 = 2 * (l & 3);
    #pragma unroll
    for (int t = 0; t < 2; t++) {
        #pragma unroll
        for (int u = 0; u < 4; u++) {
            int r = row0 + wm * 32 + t * 16 + l4;
            int col = wn * 32 + u * 8 + l2;
            float b0 = bias[col], b1 = bias[col + 1];
            float v0 = acc[t][u][0] + b0, v1 = acc[t][u][1] + b1;
            float v2 = acc[t][u][2] + b0, v3 = acc[t][u][3] + b1;
            if (which == 2) {
                float2 p0 = {v0, v1}, p1 = {v2, v3};
                *(float2*)&g_v[(size_t)r * H + col] = p0;
                *(float2*)&g_v[(size_t)(r + 8) * H + col] = p1;
            } else {
                size_t off = (size_t)which * BN * H;
                __nv_bfloat16 h0 = __float2bfloat16(v0), h1 = __float2bfloat16(v1);
                __nv_bfloat16 h2 = __float2bfloat16(v2), h3 = __float2bfloat16(v3);
                *(__nv_bfloat162*)&g_qkhi[off + (size_t)r * H + col] = __nv_bfloat162(h0, h1);
                *(__nv_bfloat162*)&g_qkhi[off + (size_t)(r + 8) * H + col] = __nv_bfloat162(h2, h3);
                __nv_bfloat162 lo0(__float2bfloat16(v0 - __bfloat162float(h0)),
                                   __float2bfloat16(v1 - __bfloat162float(h1)));
                __nv_bfloat162 lo1(__float2bfloat16(v2 - __bfloat162float(h2)),
                                   __float2bfloat16(v3 - __bfloat162float(h3)));
                *(__nv_bfloat162*)&g_qklo[off + (size_t)r * H + col] = lo0;
                *(__nv_bfloat162*)&g_qklo[off + (size_t)(r + 8) * H + col] = lo1;
            }
        }
    }
}

// ============================================================
// Kernel 2: S = Q.K^T via mma.sync bf16 hi/lo, 128x128 triangular tiles.
// ============================================================
__global__ __launch_bounds__(256) void s_mma_kernel()
{
    extern __shared__ char sms[];
    const uint32_t smb = smem_u32(sms);

    int p = blockIdx.x;
    int bi = 0;
    while (p >= NB2 - bi) { p -= NB2 - bi; bi++; }
    int bj = bi + p;
    int b = blockIdx.y;

    const int tid = threadIdx.x;
    const int w = tid >> 5, l = tid & 31;
    const int wm = w & 3, wn = w >> 2;

    const __nv_bfloat16* __restrict__ src[4] = {
        g_qkhi + (size_t)(b * N + bi * 128) * H,
        g_qklo + (size_t)(b * N + bi * 128) * H,
        g_qkhi + (size_t)BN * H + (size_t)(b * N + bj * 128) * H,
        g_qklo + (size_t)BN * H + (size_t)(b * N + bj * 128) * H
    };
    #pragma unroll
    for (int tile = 0; tile < 4; tile++) {
        #pragma unroll
        for (int it = 0; it < 4; it++) {
            int lin = tid + it * 256;
            int r = lin >> 3, c16 = lin & 7;
            uint4 v = *(const uint4*)(src[tile] + (size_t)r * H + c16 * 8);
            *(uint4*)(sms + tile * 16384 + swz128(r * 128 + c16 * 16)) = v;
        }
    }
    __syncthreads();

    float acc[2][8][4] = {};
    #pragma unroll
    for (int pass = 0; pass < 3; pass++) {
        const uint32_t aBase = smb + ((pass == 1) ? 16384 : 0);
        const uint32_t bBase = smb + ((pass == 2) ? 49152 : 32768);
        #pragma unroll
        for (int ks = 0; ks < 4; ks++) {
            const int kb = ks * 32;
            uint32_t a[2][4];
            #pragma unroll
            for (int t = 0; t < 2; t++) {
                int row = wm * 32 + t * 16 + (l & 7) + (l & 8);
                ldsm_x4(aBase + swz128(row * 128 + kb + (l & 16)), a[t][0], a[t][1], a[t][2], a[t][3]);
            }
            uint32_t bfr[4][4];
            #pragma unroll
            for (int bp = 0; bp < 4; bp++) {
                int n = wn * 64 + bp * 16 + ((l & 16) >> 1) + (l & 7);
                ldsm_x4(bBase + swz128(n * 128 + kb + ((l & 8) << 1)),
                        bfr[bp][0], bfr[bp][1], bfr[bp][2], bfr[bp][3]);
            }
            #pragma unroll
            for (int t = 0; t < 2; t++)
                #pragma unroll
                for (int u = 0; u < 8; u++)
                    mma_bf16(acc[t][u], a[t][0], a[t][1], a[t][2], a[t][3],
                             bfr[u >> 1][(u & 1) * 2], bfr[u >> 1][(u & 1) * 2 + 1]);
        }
    }

    const int l4 = l >> 2, l2 = 2 * (l & 3);
    #pragma unroll
    for (int t = 0; t < 2; t++) {
        #pragma unroll
        for (int u = 0; u < 8; u++) {
            int i = bi * 128 + wm * 32 + t * 16 + l4;
            int j = bj * 128 + wn * 64 + u * 8 + l2;
            float2 p0 = {acc[t][u][0], acc[t][u][1]};
            float2 p1 = {acc[t][u][2], acc[t][u][3]};
            *(float2*)&g_S[((size_t)(b * N + i)) * N + j] = p0;
            *(float2*)&g_S[((size_t)(b * N + i + 8)) * N + j] = p1;
        }
    }
}

// ============================================================
// Kernel 3: per-j-row: max, sum-exp, write unnormalized E (fp16) + linv.
// One block per row; whole row held in registers (8 floats/thread).
// ============================================================
__global__ __launch_bounds__(256) void ep_kernel()
{
    int row = blockIdx.x;            // b*N + j
    int j = row & (N - 1);
    const float* __restrict__ base = g_S + (size_t)row * N;
    int tid = threadIdx.x;

    float4 v0 = *(const float4*)&base[tid * 4];
    float4 v1 = *(const float4*)&base[1024 + tid * 4];
    float vv[8] = {v0.x, v0.y, v0.z, v0.w, v1.x, v1.y, v1.z, v1.w};

    // pass 1: masked max
    float m = -INFINITY;
    #pragma unroll
    for (int u = 0; u < 8; u++) {
        int i = (u < 4) ? (tid * 4 + u) : (1024 + tid * 4 + (u - 4));
        bool valid = (i >= j) && (vv[u] != 0.0f);
        if (valid) m = fmaxf(m, vv[u] * SCALE);
    }
    __shared__ float sred[256];
    sred[tid] = m;
    __syncthreads();
    #pragma unroll
    for (int o = 128; o > 0; o >>= 1) {
        if (tid < o) sred[tid] = fmaxf(sred[tid], sred[tid + o]);
        __syncthreads();
    }
    m = sred[0];
    __syncthreads();

    // pass 2: exp, row sum
    float e[8];
    float lsum = 0.0f;
    #pragma unroll
    for (int u = 0; u < 8; u++) {
        int i = (u < 4) ? (tid * 4 + u) : (1024 + tid * 4 + (u - 4));
        bool valid = (i >= j) && (vv[u] != 0.0f);
        e[u] = valid ? __expf(vv[u] * SCALE - m) : 0.0f;
        lsum += e[u];
    }
    sred[tid] = lsum;
    __syncthreads();
    #pragma unroll
    for (int o = 128; o > 0; o >>= 1) {
        if (tid < o) sred[tid] += sred[tid + o];
        __syncthreads();
    }
    if (tid == 0) g_linv[row] = 1.0f / sred[0];

    // write E (full row incl. zeros below diagonal)
    __half2 p01 = __floats2half2_rn(e[0], e[1]);
    __half2 p23 = __floats2half2_rn(e[2], e[3]);
    __half2 p45 = __floats2half2_rn(e[4], e[5]);
    __half2 p67 = __floats2half2_rn(e[6], e[7]);
    uint2 w0 = {*(uint32_t*)&p01, *(uint32_t*)&p23};
    uint2 w1 = {*(uint32_t*)&p45, *(uint32_t*)&p67};
    *(uint2*)&g_E[(size_t)row * N + tid * 4] = w0;
    *(uint2*)&g_E[(size_t)row * N + 1024 + tid * 4] = w1;
}

// ============================================================
// Kernel 3b: v' = linv_j * v, fp16 hi/lo
// ============================================================
__global__ __launch_bounds__(256) void vscale_kernel()
{
    int idx4 = blockIdx.x * 256 + threadIdx.x;   // float4 index over BN*H
    int base = idx4 * 4;
    int row = base >> 6;                          // /H
    float linv = g_linv[row];
    float4 v = *(const float4*)&g_v[base];
    float f[4] = {v.x * linv, v.y * linv, v.z * linv, v.w * linv};
    __half hi[4], lo[4];
    #pragma unroll
    for (int u = 0; u < 4; u++) {
        hi[u] = __float2half(f[u]);
        lo[u] = __float2half(f[u] - __half2float(hi[u]));
    }
    __half2 h01(hi[0], hi[1]), h23(hi[2], hi[3]);
    __half2 l01(lo[0], lo[1]), l23(lo[2], lo[3]);
    uint2 wh = {*(uint32_t*)&h01, *(uint32_t*)&h23};
    uint2 wl = {*(uint32_t*)&l01, *(uint32_t*)&l23};
    *(uint2*)&g_vhi[base] = wh;
    *(uint2*)&g_vlo[base] = wl;
}

// ============================================================
// Kernel 4: AV partials via fp16 mma.  out[i,h] = sum_j E[j,i] * v'[j,h].
// CTA 128i x 64h, 8 warps (4i x 2h), warp 32x32. j-chunks of 256.
// E loaded [j][i] and trans-ldmatrix'd for A; V' [j][h] trans for B.
// ============================================================
__global__ __launch_bounds__(256) void av_mma_kernel()
{
    int p = blockIdx.x, b = blockIdx.y;
    int bi = 0;
    for (;;) {
        int nc = ((2 * bi + 1) >> 2) + 1;
        if (p < nc) break;
        p -= nc; bi++;
    }
    int chunk = p;
    int i0 = bi * 128;
    int jb0 = chunk * 4;
    int jb_end = min(jb0 + 4, 2 * bi + 2);

    __shared__ __align__(16) char smE[16384];   // 2 halves: [half][64j][128B(64i fp16)] swz
    __shared__ __align__(16) char smVh[8192];   // [64j][128B(64h fp16)] swz
    __shared__ __align__(16) char smVl[8192];
    const uint32_t eb = smem_u32(smE), vhb = smem_u32(smVh), vlb = smem_u32(smVl);

    int tid = threadIdx.x;
    int w = tid >> 5, l = tid & 31;
    int im = w & 3, ih = w >> 2;

    float acc[2][4][4] = {};

    for (int jb = jb0; jb < jb_end; jb++) {
        int j0 = jb * 64;
        __syncthreads();
        // E tile: 64 rows x 256B
        #pragma unroll
        for (int it = 0; it < 4; it++) {
            int lin = tid + it * 256;            // 0..1023
            int jr = lin >> 4, c16 = lin & 15;
            int half = c16 >> 3, ic16 = c16 & 7;
            uint4 t = *(const uint4*)&g_E[((size_t)b * N + j0 + jr) * N + i0 + c16 * 8];
            *(uint4*)(smE + half * 8192 + swz128(jr * 128 + ic16 * 16)) = t;
        }
        // V' hi/lo tiles: 64 rows x 128B each
        #pragma unroll
        for (int it = 0; it < 2; it++) {
            int lin = tid + it * 256;            // 0..511
            int jr = lin >> 3, c16 = lin & 7;
            uint4 th = *(const uint4*)&g_vhi[((size_t)b * N + j0 + jr) * H + c16 * 8];
            uint4 tl = *(const uint4*)&g_vlo[((size_t)b * N + j0 + jr) * H + c16 * 8];
            uint32_t off = swz128(jr * 128 + c16 * 16);
            *(uint4*)(smVh + off) = th;
            *(uint4*)(smVl + off) = tl;
        }
        __syncthreads();

        #pragma unroll
        for (int ks = 0; ks < 4; ks++) {
            // A frags: E^T, via trans ldmatrix
            uint32_t a[2][4];
            #pragma unroll
            for (int t = 0; t < 2; t++) {
                int il = im * 32 + t * 16;
                int half = il >> 6, iin = il & 63;
                int jr = ks * 16 + (l & 7) + ((l & 16) >> 1);
                int ic = iin + (l & 8);
                ldsm_x4_t(eb + half * 8192 + swz128(jr * 128 + ic * 2),
                          a[t][0], a[t][1], a[t][2], a[t][3]);
            }
            // B frags: V' row-major [k][n] via trans ldmatrix
            uint32_t bh[2][4], bl[2][4];
            #pragma unroll
            for (int s2 = 0; s2 < 2; s2++) {
                int jrb = ks * 16 + (l & 7) + (l & 8);
                int hc = ih * 32 + s2 * 16 + ((l & 16) >> 1);
                uint32_t off = swz128(jrb * 128 + hc * 2);
                ldsm_x4_t(vhb + off, bh[s2][0], bh[s2][1], bh[s2][2], bh[s2][3]);
                ldsm_x4_t(vlb + off, bl[s2][0], bl[s2][1], bl[s2][2], bl[s2][3]);
            }
            #pragma unroll
            for (int t = 0; t < 2; t++)
                #pragma unroll
                for (int s2 = 0; s2 < 2; s2++)
                    #pragma unroll
                    for (int n8 = 0; n8 < 2; n8++) {
                        int u = s2 * 2 + n8;
                        mma_fp16(acc[t][u], a[t][0], a[t][1], a[t][2], a[t][3],
                                 bh[s2][2 * n8], bh[s2][2 * n8 + 1]);
                        mma_fp16(acc[t][u], a[t][0], a[t][1], a[t][2], a[t][3],
                                 bl[s2][2 * n8], bl[s2][2 * n8 + 1]);
                    }
        }
    }

    const int l4 = l >> 2, l2 = 2 * (l & 3);
    #pragma unroll
    for (int t = 0; t < 2; t++) {
        #pragma unroll
        for (int u = 0; u < 4; u++) {
            int i = i0 + im * 32 + t * 16 + l4;
            int h = ih * 32 + u * 8 + l2;
            float2 p0 = {acc[t][u][0], acc[t][u][1]};
            float2 p1 = {acc[t][u][2], acc[t][u][3]};
            *(float2*)&g_part[((size_t)chunk * BN + b * N + i) * H + h] = p0;
            *(float2*)&g_part[((size_t)chunk * BN + b * N + i + 8) * H + h] = p1;
        }
    }
}

// ============================================================
// Kernel 5: reduce partial chunks
// ============================================================
__global__ __launch_bounds__(256) void reduce_kernel(float* __restrict__ out)
{
    int idx = blockIdx.x * 256 + threadIdx.x;
    if (idx >= BN * H) return;
    int row = idx / H;
    int i = row & (N - 1);
    int nch = (i >> 8) + 1;
    float s = 0.0f;
    for (int c = 0; c < nch; c++)
        s += g_part[(size_t)c * BN * H + idx];
    out[idx] = s;
}

// ============================================================
extern "C" void kernel_launch(void* const* d_in, const int* in_sizes, int n_in,
                              void* d_out, int out_size)
{
    const float* x  = (const float*)d_in[0];
    const float* Wq = (const float*)d_in[1];
    const float* bq = (const float*)d_in[2];
    const float* Wk = (const float*)d_in[3];
    const float* bk = (const float*)d_in[4];
    const float* Wv = (const float*)d_in[5];
    const float* bv = (const float*)d_in[6];
    float* out = (float*)d_out;

    cudaFuncSetAttribute(s_mma_kernel, cudaFuncAttributeMaxDynamicSharedMemorySize, 65536);

    convert_x_kernel<<<(BN * D) / 1024, 256>>>(x);
    convert_w_kernel<<<dim3(H, 3), 256>>>(Wq, Wk, Wv);
    qkv_mma_kernel<<<dim3(BN / 128, 3), 256>>>(bq, bk, bv);
    s_mma_kernel<<<dim3(NPAIR2, B), 256, 65536>>>();
    ep_kernel<<<BN, 256>>>();
    vscale_kernel<<<(BN * H) / 1024, 256>>>();
    av_mma_kernel<<<dim3(72, B), 256>>>();
    reduce_kernel<<<(BN * H + 255) / 256, 256>>>(out);
}

// round 10
// speedup vs baseline: 2.4650x; 1.2461x over previous
#include <cuda_runtime.h>
#include <cuda_bf16.h>
#include <cuda_fp16.h>
#include <math.h>
#include <stdint.h>

#define B 4
#define N 2048
#define D 1024
#define H 64
#define BN (B*N)            // 8192
#define SCALE 0.125f
#define NB2 16              // N/128
#define NPAIR2 (NB2*(NB2+1)/2)   // 136
#define NCHUNK 8

// ---- scratch (device globals) ----
__device__ __nv_bfloat16 g_bthi[3*H*D];   // [which*64+n][k] transposed weights, hi
__device__ __nv_bfloat16 g_btlo[3*H*D];
__device__ __nv_bfloat16 g_qkhi[2*BN*H];  // q,k bf16 hi ([row][64])
__device__ __nv_bfloat16 g_qklo[2*BN*H];
__device__ float g_v[BN*H];
__device__ float g_S[(size_t)B*N*N];
__device__ __half g_E[(size_t)B*N*N];     // unnormalized exp/l-folded-in-V, [b][j][i]
__device__ __half g_vhi[BN*H];            // v * linv, fp16 hi
__device__ __half g_vlo[BN*H];
__device__ float g_part[(size_t)NCHUNK*BN*H];

// ============================================================
// helpers
// ============================================================
__device__ __forceinline__ uint32_t smem_u32(const void* p) {
    uint32_t a;
    asm("{ .reg .u64 t; cvta.to.shared.u64 t, %1; cvt.u32.u64 %0, t; }" : "=r"(a) : "l"(p));
    return a;
}
static __device__ __forceinline__ uint32_t swz128(uint32_t off) { return off ^ ((off >> 3) & 0x70); }

__device__ __forceinline__ void ldsm_x4(uint32_t addr, uint32_t& r0, uint32_t& r1, uint32_t& r2, uint32_t& r3) {
    asm volatile("ldmatrix.sync.aligned.m8n8.x4.shared.b16 {%0,%1,%2,%3}, [%4];"
                 : "=r"(r0), "=r"(r1), "=r"(r2), "=r"(r3) : "r"(addr));
}
__device__ __forceinline__ void ldsm_x4_t(uint32_t addr, uint32_t& r0, uint32_t& r1, uint32_t& r2, uint32_t& r3) {
    asm volatile("ldmatrix.sync.aligned.m8n8.x4.trans.shared.b16 {%0,%1,%2,%3}, [%4];"
                 : "=r"(r0), "=r"(r1), "=r"(r2), "=r"(r3) : "r"(addr));
}
__device__ __forceinline__ void mma_bf16(float* c, const uint32_t* a, uint32_t b0, uint32_t b1) {
    asm volatile("mma.sync.aligned.m16n8k16.row.col.f32.bf16.bf16.f32 "
                 "{%0,%1,%2,%3}, {%4,%5,%6,%7}, {%8,%9}, {%0,%1,%2,%3};"
                 : "+f"(c[0]), "+f"(c[1]), "+f"(c[2]), "+f"(c[3])
                 : "r"(a[0]), "r"(a[1]), "r"(a[2]), "r"(a[3]), "r"(b0), "r"(b1));
}
__device__ __forceinline__ void mma_fp16(float* c, const uint32_t* a, uint32_t b0, uint32_t b1) {
    asm volatile("mma.sync.aligned.m16n8k16.row.col.f32.f16.f16.f32 "
                 "{%0,%1,%2,%3}, {%4,%5,%6,%7}, {%8,%9}, {%0,%1,%2,%3};"
                 : "+f"(c[0]), "+f"(c[1]), "+f"(c[2]), "+f"(c[3])
                 : "r"(a[0]), "r"(a[1]), "r"(a[2]), "r"(a[3]), "r"(b0), "r"(b1));
}
#define CP_ASYNC16(dst, src) asm volatile("cp.async.cg.shared.global [%0], [%1], 16;" :: "r"(dst), "l"(src))
#define CP_COMMIT() asm volatile("cp.async.commit_group;" ::: "memory")
#define CP_WAIT1() asm volatile("cp.async.wait_group 1;" ::: "memory")
#define CP_WAIT0() asm volatile("cp.async.wait_group 0;" ::: "memory")

// ============================================================
// Kernel 0: transpose+split W -> [which*64+n][k], hi/lo
// ============================================================
__global__ __launch_bounds__(256) void convert_w_kernel(
    const float* __restrict__ Wq, const float* __restrict__ Wk, const float* __restrict__ Wv)
{
    int n = blockIdx.x;
    int which = blockIdx.y;
    const float* __restrict__ W = (which == 0) ? Wq : (which == 1) ? Wk : Wv;
    int base = which * H * D + n * D;
    for (int it = 0; it < 4; it++) {
        int k = threadIdx.x + it * 256;
        float w = W[(size_t)k * H + n];
        __nv_bfloat16 hi = __float2bfloat16(w);
        __nv_bfloat16 lo = __float2bfloat16(w - __bfloat162float(hi));
        g_bthi[base + k] = hi;
        g_btlo[base + k] = lo;
    }
}

// ============================================================
// Kernel 1: fused QKV. CTA tile 64(M) x 192(N=q|k|v), K-chunks of 64.
// Per chunk one pass: a_hi*b_hi + a_lo*b_hi + a_hi*b_lo.
// x loaded fp32 (reg-staged), converted to hi/lo bf16 smem tiles in-kernel.
// 8 warps: 2m x 4n, warp tile 32x48.
// Dyn smem: 2 bufs x (Ahi 8K + Alo 8K + Bhi 24K + Blo 24K) = 128KB.
// ============================================================
#define QKV_BUFSZ 65536
#define QAHI(b) ((b) * QKV_BUFSZ)
#define QALO(b) ((b) * QKV_BUFSZ + 8192)
#define QBHI(b) ((b) * QKV_BUFSZ + 16384)
#define QBLO(b) ((b) * QKV_BUFSZ + 40960)

__global__ __launch_bounds__(256, 1) void qkv_mma_kernel(
    const float* __restrict__ x,
    const float* __restrict__ bq, const float* __restrict__ bk, const float* __restrict__ bv)
{
    extern __shared__ __align__(16) char sm[];
    const uint32_t smb = smem_u32(sm);

    const int tid = threadIdx.x;
    const int w = tid >> 5, l = tid & 31;
    const int wm = w & 1, wn = w >> 1;
    const int row0 = blockIdx.x * 64;

    float4 xr[2][2];
    float acc[2][6][4] = {};

    auto prefetch = [&](int c) {
        int k0 = c * 64;
        #pragma unroll
        for (int it = 0; it < 2; it++) {
            int lin = tid + it * 256;
            int r = lin >> 3, c8 = lin & 7;
            const float* src = x + (size_t)(row0 + r) * D + k0 + c8 * 8;
            xr[it][0] = *(const float4*)src;
            xr[it][1] = *(const float4*)(src + 4);
        }
    };
    auto sts_convert = [&](int buf) {
        #pragma unroll
        for (int it = 0; it < 2; it++) {
            int lin = tid + it * 256;
            int r = lin >> 3, c8 = lin & 7;
            float f[8] = {xr[it][0].x, xr[it][0].y, xr[it][0].z, xr[it][0].w,
                          xr[it][1].x, xr[it][1].y, xr[it][1].z, xr[it][1].w};
            __nv_bfloat16 hi[8], lo[8];
            #pragma unroll
            for (int u = 0; u < 8; u++) {
                hi[u] = __float2bfloat16(f[u]);
                lo[u] = __float2bfloat16(f[u] - __bfloat162float(hi[u]));
            }
            uint32_t off = swz128(r * 128 + c8 * 16);
            __nv_bfloat162 h2[4] = {{hi[0],hi[1]},{hi[2],hi[3]},{hi[4],hi[5]},{hi[6],hi[7]}};
            __nv_bfloat162 l2[4] = {{lo[0],lo[1]},{lo[2],lo[3]},{lo[4],lo[5]},{lo[6],lo[7]}};
            *(uint4*)(sm + QAHI(buf) + off) = *(uint4*)h2;
            *(uint4*)(sm + QALO(buf) + off) = *(uint4*)l2;
        }
    };
    auto issueB = [&](int c, int buf) {
        int k0 = c * 64;
        #pragma unroll
        for (int it = 0; it < 6; it++) {
            int lin = tid + it * 256;          // 0..1535 -> 192 rows x 8 c16
            int r = lin >> 3, c16 = lin & 7;
            uint32_t off = swz128(r * 128 + c16 * 16);
            CP_ASYNC16(smb + QBHI(buf) + off, g_bthi + (size_t)r * D + k0 + c16 * 8);
            CP_ASYNC16(smb + QBLO(buf) + off, g_btlo + (size_t)r * D + k0 + c16 * 8);
        }
    };

    prefetch(0);
    issueB(0, 0); CP_COMMIT();

    for (int c = 0; c < 16; c++) {
        const int buf = c & 1;
        sts_convert(buf);
        if (c < 15) {
            issueB(c + 1, buf ^ 1); CP_COMMIT();
            prefetch(c + 1);
            CP_WAIT1();
        } else {
            CP_WAIT0();
        }
        __syncthreads();

        const uint32_t aHi = smb + QAHI(buf), aLo = smb + QALO(buf);
        const uint32_t bHi = smb + QBHI(buf), bLo = smb + QBLO(buf);
        #pragma unroll
        for (int ks = 0; ks < 4; ks++) {
            const int kb = ks * 32;
            uint32_t ah[2][4], al[2][4];
            #pragma unroll
            for (int t = 0; t < 2; t++) {
                int row = wm * 32 + t * 16 + (l & 7) + (l & 8);
                uint32_t off = swz128(row * 128 + kb + (l & 16));
                ldsm_x4(aHi + off, ah[t][0], ah[t][1], ah[t][2], ah[t][3]);
                ldsm_x4(aLo + off, al[t][0], al[t][1], al[t][2], al[t][3]);
            }
            uint32_t bh[3][4], bl[3][4];
            #pragma unroll
            for (int bp = 0; bp < 3; bp++) {
                int n = wn * 48 + bp * 16 + ((l & 16) >> 1) + (l & 7);
                uint32_t off = swz128(n * 128 + kb + ((l & 8) << 1));
                ldsm_x4(bHi + off, bh[bp][0], bh[bp][1], bh[bp][2], bh[bp][3]);
                ldsm_x4(bLo + off, bl[bp][0], bl[bp][1], bl[bp][2], bl[bp][3]);
            }
            #pragma unroll
            for (int t = 0; t < 2; t++)
                #pragma unroll
                for (int u = 0; u < 6; u++) {
                    int bp = u >> 1, s = (u & 1) * 2;
                    mma_bf16(acc[t][u], ah[t], bh[bp][s], bh[bp][s + 1]);
                    mma_bf16(acc[t][u], al[t], bh[bp][s], bh[bp][s + 1]);
                    mma_bf16(acc[t][u], ah[t], bl[bp][s], bl[bp][s + 1]);
                }
        }
        __syncthreads();
    }

    const int l4 = l >> 2, l2 = 2 * (l & 3);
    #pragma unroll
    for (int t = 0; t < 2; t++) {
        #pragma unroll
        for (int u = 0; u < 6; u++) {
            int r = row0 + wm * 32 + t * 16 + l4;
            int nn = wn * 48 + u * 8 + l2;
            int which = nn >> 6, col = nn & 63;
            const float* bias = (which == 0) ? bq : (which == 1) ? bk : bv;
            float b0 = bias[col], b1 = bias[col + 1];
            float v0 = acc[t][u][0] + b0, v1 = acc[t][u][1] + b1;
            float v2 = acc[t][u][2] + b0, v3 = acc[t][u][3] + b1;
            if (which == 2) {
                float2 p0 = {v0, v1}, p1 = {v2, v3};
                *(float2*)&g_v[(size_t)r * H + col] = p0;
                *(float2*)&g_v[(size_t)(r + 8) * H + col] = p1;
            } else {
                size_t off = (size_t)which * BN * H;
                __nv_bfloat16 h0 = __float2bfloat16(v0), h1 = __float2bfloat16(v1);
                __nv_bfloat16 h2 = __float2bfloat16(v2), h3 = __float2bfloat16(v3);
                *(__nv_bfloat162*)&g_qkhi[off + (size_t)r * H + col] = __nv_bfloat162(h0, h1);
                *(__nv_bfloat162*)&g_qkhi[off + (size_t)(r + 8) * H + col] = __nv_bfloat162(h2, h3);
                __nv_bfloat162 lo0(__float2bfloat16(v0 - __bfloat162float(h0)),
                                   __float2bfloat16(v1 - __bfloat162float(h1)));
                __nv_bfloat162 lo1(__float2bfloat16(v2 - __bfloat162float(h2)),
                                   __float2bfloat16(v3 - __bfloat162float(h3)));
                *(__nv_bfloat162*)&g_qklo[off + (size_t)r * H + col] = lo0;
                *(__nv_bfloat162*)&g_qklo[off + (size_t)(r + 8) * H + col] = lo1;
            }
        }
    }
}

// ============================================================
// Kernel 2: S = Q.K^T, 128x128 triangular tiles, 512 threads (4m x 4n warps).
// ============================================================
__global__ __launch_bounds__(512) void s_mma_kernel()
{
    extern __shared__ char sms[];
    const uint32_t smb = smem_u32(sms);

    int p = blockIdx.x;
    int bi = 0;
    while (p >= NB2 - bi) { p -= NB2 - bi; bi++; }
    int bj = bi + p;
    int b = blockIdx.y;

    const int tid = threadIdx.x;
    const int w = tid >> 5, l = tid & 31;
    const int wm = w & 3, wn = w >> 2;

    const __nv_bfloat16* __restrict__ src[4] = {
        g_qkhi + (size_t)(b * N + bi * 128) * H,
        g_qklo + (size_t)(b * N + bi * 128) * H,
        g_qkhi + (size_t)BN * H + (size_t)(b * N + bj * 128) * H,
        g_qklo + (size_t)BN * H + (size_t)(b * N + bj * 128) * H
    };
    #pragma unroll
    for (int tile = 0; tile < 4; tile++) {
        #pragma unroll
        for (int it = 0; it < 2; it++) {
            int lin = tid + it * 512;
            int r = lin >> 3, c16 = lin & 7;
            uint4 v = *(const uint4*)(src[tile] + (size_t)r * H + c16 * 8);
            *(uint4*)(sms + tile * 16384 + swz128(r * 128 + c16 * 16)) = v;
        }
    }
    __syncthreads();

    float acc[2][4][4] = {};
    #pragma unroll
    for (int pass = 0; pass < 3; pass++) {
        const uint32_t aBase = smb + ((pass == 1) ? 16384 : 0);
        const uint32_t bBase = smb + ((pass == 2) ? 49152 : 32768);
        #pragma unroll
        for (int ks = 0; ks < 4; ks++) {
            const int kb = ks * 32;
            uint32_t a[2][4];
            #pragma unroll
            for (int t = 0; t < 2; t++) {
                int row = wm * 32 + t * 16 + (l & 7) + (l & 8);
                ldsm_x4(aBase + swz128(row * 128 + kb + (l & 16)), a[t][0], a[t][1], a[t][2], a[t][3]);
            }
            uint32_t bfr[2][4];
            #pragma unroll
            for (int bp = 0; bp < 2; bp++) {
                int n = wn * 32 + bp * 16 + ((l & 16) >> 1) + (l & 7);
                ldsm_x4(bBase + swz128(n * 128 + kb + ((l & 8) << 1)),
                        bfr[bp][0], bfr[bp][1], bfr[bp][2], bfr[bp][3]);
            }
            #pragma unroll
            for (int t = 0; t < 2; t++)
                #pragma unroll
                for (int u = 0; u < 4; u++)
                    mma_bf16(acc[t][u], a[t], bfr[u >> 1][(u & 1) * 2], bfr[u >> 1][(u & 1) * 2 + 1]);
        }
    }

    const int l4 = l >> 2, l2 = 2 * (l & 3);
    #pragma unroll
    for (int t = 0; t < 2; t++) {
        #pragma unroll
        for (int u = 0; u < 4; u++) {
            int i = bi * 128 + wm * 32 + t * 16 + l4;
            int j = bj * 128 + wn * 32 + u * 8 + l2;
            float2 p0 = {acc[t][u][0], acc[t][u][1]};
            float2 p1 = {acc[t][u][2], acc[t][u][3]};
            *(float2*)&g_S[((size_t)(b * N + i)) * N + j] = p0;
            *(float2*)&g_S[((size_t)(b * N + i + 8)) * N + j] = p1;
        }
    }
}

// ============================================================
// Kernel 3: per-j-row softmax: max, exp, sum; write E (fp16, only i >= j&~127);
// fused v' = linv*v (fp16 hi/lo).
// ============================================================
__global__ __launch_bounds__(256) void ep_kernel()
{
    int row = blockIdx.x;            // b*N + j
    int j = row & (N - 1);
    int i0 = j & ~127;               // av only reads i >= this
    const float* __restrict__ base = g_S + (size_t)row * N;
    int tid = threadIdx.x;

    float vv[8];
    #pragma unroll
    for (int it = 0; it < 2; it++) {
        int i = i0 + tid * 4 + it * 1024;
        if (i < N) {
            float4 t = *(const float4*)&base[i];
            vv[it*4+0]=t.x; vv[it*4+1]=t.y; vv[it*4+2]=t.z; vv[it*4+3]=t.w;
        } else {
            vv[it*4+0]=vv[it*4+1]=vv[it*4+2]=vv[it*4+3]=0.0f;
        }
    }

    // pass 1: masked max
    float m = -INFINITY;
    #pragma unroll
    for (int it = 0; it < 2; it++)
        #pragma unroll
        for (int u = 0; u < 4; u++) {
            int i = i0 + tid * 4 + it * 1024 + u;
            float s = vv[it*4+u];
            if (i < N && i >= j && s != 0.0f) m = fmaxf(m, s * SCALE);
        }
    __shared__ float sred[256];
    sred[tid] = m;
    __syncthreads();
    #pragma unroll
    for (int o = 128; o > 0; o >>= 1) {
        if (tid < o) sred[tid] = fmaxf(sred[tid], sred[tid + o]);
        __syncthreads();
    }
    m = sred[0];
    __syncthreads();

    // pass 2: exp + sum + write E
    float lsum = 0.0f;
    #pragma unroll
    for (int it = 0; it < 2; it++) {
        int ib = i0 + tid * 4 + it * 1024;
        float e[4];
        #pragma unroll
        for (int u = 0; u < 4; u++) {
            int i = ib + u;
            float s = vv[it*4+u];
            bool valid = (i < N) && (i >= j) && (s != 0.0f);
            e[u] = valid ? __expf(s * SCALE - m) : 0.0f;
            lsum += e[u];
        }
        if (ib < N) {
            __half2 p01 = __floats2half2_rn(e[0], e[1]);
            __half2 p23 = __floats2half2_rn(e[2], e[3]);
            uint2 wo = {*(uint32_t*)&p01, *(uint32_t*)&p23};
            *(uint2*)&g_E[(size_t)row * N + ib] = wo;
        }
    }
    sred[tid] = lsum;
    __syncthreads();
    #pragma unroll
    for (int o = 128; o > 0; o >>= 1) {
        if (tid < o) sred[tid] += sred[tid + o];
        __syncthreads();
    }
    float linv = 1.0f / sred[0];

    // fused v scaling: v'[j] = linv * v[j], fp16 hi/lo
    if (tid < 16) {
        float4 v = *(const float4*)&g_v[(size_t)row * H + tid * 4];
        float f[4] = {v.x * linv, v.y * linv, v.z * linv, v.w * linv};
        __half hi[4], lo[4];
        #pragma unroll
        for (int u = 0; u < 4; u++) {
            hi[u] = __float2half(f[u]);
            lo[u] = __float2half(f[u] - __half2float(hi[u]));
        }
        __half2 h01(hi[0], hi[1]), h23(hi[2], hi[3]);
        __half2 l01(lo[0], lo[1]), l23(lo[2], lo[3]);
        uint2 wh = {*(uint32_t*)&h01, *(uint32_t*)&h23};
        uint2 wl = {*(uint32_t*)&l01, *(uint32_t*)&l23};
        *(uint2*)&g_vhi[(size_t)row * H + tid * 4] = wh;
        *(uint2*)&g_vlo[(size_t)row * H + tid * 4] = wl;
    }
}

// ============================================================
// Kernel 4: AV partials via fp16 mma, 512 threads (4i x 4h warps, warp 32x16).
// ============================================================
__global__ __launch_bounds__(512) void av_mma_kernel()
{
    int p = blockIdx.x, b = blockIdx.y;
    int bi = 0;
    for (;;) {
        int nc = ((2 * bi + 1) >> 2) + 1;
        if (p < nc) break;
        p -= nc; bi++;
    }
    int chunk = p;
    int i0 = bi * 128;
    int jb0 = chunk * 4;
    int jb_end = min(jb0 + 4, 2 * bi + 2);

    __shared__ __align__(16) char smE[16384];   // [half][64j][128B(64i fp16)] swz
    __shared__ __align__(16) char smVh[8192];
    __shared__ __align__(16) char smVl[8192];
    const uint32_t eb = smem_u32(smE), vhb = smem_u32(smVh), vlb = smem_u32(smVl);

    int tid = threadIdx.x;
    int w = tid >> 5, l = tid & 31;
    int im = w & 3, ih = w >> 2;

    float acc[2][2][4] = {};

    for (int jb = jb0; jb < jb_end; jb++) {
        int j0 = jb * 64;
        __syncthreads();
        #pragma unroll
        for (int it = 0; it < 2; it++) {
            int lin = tid + it * 512;            // 0..1023
            int jr = lin >> 4, c16 = lin & 15;
            int half = c16 >> 3, ic16 = c16 & 7;
            uint4 t = *(const uint4*)&g_E[((size_t)b * N + j0 + jr) * N + i0 + c16 * 8];
            *(uint4*)(smE + half * 8192 + swz128(jr * 128 + ic16 * 16)) = t;
        }
        {
            int jr = tid >> 3, c16 = tid & 7;    // 512 = 64 x 8
            uint4 th = *(const uint4*)&g_vhi[((size_t)b * N + j0 + jr) * H + c16 * 8];
            uint4 tl = *(const uint4*)&g_vlo[((size_t)b * N + j0 + jr) * H + c16 * 8];
            uint32_t off = swz128(jr * 128 + c16 * 16);
            *(uint4*)(smVh + off) = th;
            *(uint4*)(smVl + off) = tl;
        }
        __syncthreads();

        #pragma unroll
        for (int ks = 0; ks < 4; ks++) {
            uint32_t a[2][4];
            #pragma unroll
            for (int t = 0; t < 2; t++) {
                int il = im * 32 + t * 16;
                int half = il >> 6, iin = il & 63;
                int jr = ks * 16 + (l & 7) + ((l & 16) >> 1);
                int ic = iin + (l & 8);
                ldsm_x4_t(eb + half * 8192 + swz128(jr * 128 + ic * 2),
                          a[t][0], a[t][1], a[t][2], a[t][3]);
            }
            uint32_t bh[4], bl[4];
            {
                int jrb = ks * 16 + (l & 7) + (l & 8);
                int hc = ih * 16 + ((l & 16) >> 1);
                uint32_t off = swz128(jrb * 128 + hc * 2);
                ldsm_x4_t(vhb + off, bh[0], bh[1], bh[2], bh[3]);
                ldsm_x4_t(vlb + off, bl[0], bl[1], bl[2], bl[3]);
            }
            #pragma unroll
            for (int t = 0; t < 2; t++)
                #pragma unroll
                for (int n8 = 0; n8 < 2; n8++) {
                    mma_fp16(acc[t][n8], a[t], bh[2 * n8], bh[2 * n8 + 1]);
                    mma_fp16(acc[t][n8], a[t], bl[2 * n8], bl[2 * n8 + 1]);
                }
        }
    }

    const int l4 = l >> 2, l2 = 2 * (l & 3);
    #pragma unroll
    for (int t = 0; t < 2; t++) {
        #pragma unroll
        for (int n8 = 0; n8 < 2; n8++) {
            int i = i0 + im * 32 + t * 16 + l4;
            int h = ih * 16 + n8 * 8 + l2;
            float2 p0 = {acc[t][n8][0], acc[t][n8][1]};
            float2 p1 = {acc[t][n8][2], acc[t][n8][3]};
            *(float2*)&g_part[((size_t)chunk * BN + b * N + i) * H + h] = p0;
            *(float2*)&g_part[((size_t)chunk * BN + b * N + i + 8) * H + h] = p1;
        }
    }
}

// ============================================================
// Kernel 5: reduce partial chunks
// ============================================================
__global__ __launch_bounds__(256) void reduce_kernel(float* __restrict__ out)
{
    int idx = blockIdx.x * 256 + threadIdx.x;
    if (idx >= BN * H) return;
    int row = idx / H;
    int i = row & (N - 1);
    int nch = (i >> 8) + 1;
    float s = 0.0f;
    for (int c = 0; c < nch; c++)
        s += g_part[(size_t)c * BN * H + idx];
    out[idx] = s;
}

// ============================================================
extern "C" void kernel_launch(void* const* d_in, const int* in_sizes, int n_in,
                              void* d_out, int out_size)
{
    const float* x  = (const float*)d_in[0];
    const float* Wq = (const float*)d_in[1];
    const float* bq = (const float*)d_in[2];
    const float* Wk = (const float*)d_in[3];
    const float* bk = (const float*)d_in[4];
    const float* Wv = (const float*)d_in[5];
    const float* bv = (const float*)d_in[6];
    float* out = (float*)d_out;

    cudaFuncSetAttribute(qkv_mma_kernel, cudaFuncAttributeMaxDynamicSharedMemorySize, 2 * QKV_BUFSZ);
    cudaFuncSetAttribute(s_mma_kernel, cudaFuncAttributeMaxDynamicSharedMemorySize, 65536);

    convert_w_kernel<<<dim3(H, 3), 256>>>(Wq, Wk, Wv);
    qkv_mma_kernel<<<BN / 64, 256, 2 * QKV_BUFSZ>>>(x, bq, bk, bv);
    s_mma_kernel<<<dim3(NPAIR2, B), 512, 65536>>>();
    ep_kernel<<<BN, 256>>>();
    av_mma_kernel<<<dim3(72, B), 512>>>();
    reduce_kernel<<<(BN * H + 255) / 256, 256>>>(out);
}

// round 13
// speedup vs baseline: 2.6866x; 1.0899x over previous
#include <cuda_runtime.h>
#include <cuda_bf16.h>
#include <cuda_fp16.h>
#include <math.h>
#include <stdint.h>

#define B 4
#define N 2048
#define D 1024
#define H 64
#define BN (B*N)            // 8192
#define SCALE 0.125f
#define NB2 16              // N/128
#define NPAIR2 (NB2*(NB2+1)/2)   // 136
#define NCHUNK 8

// ---- scratch (device globals) ----
__device__ __nv_bfloat16 g_bthi[3*H*D];   // [which*64+n][k] transposed weights, hi
__device__ __nv_bfloat16 g_btlo[3*H*D];
__device__ __nv_bfloat16 g_qkhi[2*BN*H];  // q,k bf16 hi ([row][64])
__device__ __nv_bfloat16 g_qklo[2*BN*H];
__device__ float g_v[BN*H];
__device__ float g_S[(size_t)B*N*N];
__device__ __half g_E[(size_t)B*N*N];     // unnormalized exp, [b][j][i]
__device__ __half g_vhi[BN*H];            // v * linv, fp16 hi
__device__ __half g_vlo[BN*H];
__device__ float g_part[(size_t)NCHUNK*BN*H];

// ============================================================
// helpers
// ============================================================
__device__ __forceinline__ uint32_t smem_u32(const void* p) {
    uint32_t a;
    asm("{ .reg .u64 t; cvta.to.shared.u64 t, %1; cvt.u32.u64 %0, t; }" : "=r"(a) : "l"(p));
    return a;
}
static __device__ __forceinline__ uint32_t swz128(uint32_t off) { return off ^ ((off >> 3) & 0x70); }

__device__ __forceinline__ float ex2f(float x) {
    float r;
    asm("ex2.approx.ftz.f32 %0, %1;" : "=f"(r) : "f"(x));
    return r;
}

__device__ __forceinline__ void ldsm_x4(uint32_t addr, uint32_t& r0, uint32_t& r1, uint32_t& r2, uint32_t& r3) {
    asm volatile("ldmatrix.sync.aligned.m8n8.x4.shared.b16 {%0,%1,%2,%3}, [%4];"
                 : "=r"(r0), "=r"(r1), "=r"(r2), "=r"(r3) : "r"(addr));
}
__device__ __forceinline__ void ldsm_x4_t(uint32_t addr, uint32_t& r0, uint32_t& r1, uint32_t& r2, uint32_t& r3) {
    asm volatile("ldmatrix.sync.aligned.m8n8.x4.trans.shared.b16 {%0,%1,%2,%3}, [%4];"
                 : "=r"(r0), "=r"(r1), "=r"(r2), "=r"(r3) : "r"(addr));
}
__device__ __forceinline__ void mma_bf16(float* c, const uint32_t* a, uint32_t b0, uint32_t b1) {
    asm volatile("mma.sync.aligned.m16n8k16.row.col.f32.bf16.bf16.f32 "
                 "{%0,%1,%2,%3}, {%4,%5,%6,%7}, {%8,%9}, {%0,%1,%2,%3};"
                 : "+f"(c[0]), "+f"(c[1]), "+f"(c[2]), "+f"(c[3])
                 : "r"(a[0]), "r"(a[1]), "r"(a[2]), "r"(a[3]), "r"(b0), "r"(b1));
}
__device__ __forceinline__ void mma_fp16(float* c, const uint32_t* a, uint32_t b0, uint32_t b1) {
    asm volatile("mma.sync.aligned.m16n8k16.row.col.f32.f16.f16.f32 "
                 "{%0,%1,%2,%3}, {%4,%5,%6,%7}, {%8,%9}, {%0,%1,%2,%3};"
                 : "+f"(c[0]), "+f"(c[1]), "+f"(c[2]), "+f"(c[3])
                 : "r"(a[0]), "r"(a[1]), "r"(a[2]), "r"(a[3]), "r"(b0), "r"(b1));
}
#define CP_ASYNC16(dst, src) asm volatile("cp.async.cg.shared.global [%0], [%1], 16;" :: "r"(dst), "l"(src))
#define CP_COMMIT() asm volatile("cp.async.commit_group;" ::: "memory")
#define CP_WAIT1() asm volatile("cp.async.wait_group 1;" ::: "memory")
#define CP_WAIT0() asm volatile("cp.async.wait_group 0;" ::: "memory")

// ============================================================
// Kernel 0: transpose+split W -> [which*64+n][k], hi/lo
// ============================================================
__global__ __launch_bounds__(256) void convert_w_kernel(
    const float* __restrict__ Wq, const float* __restrict__ Wk, const float* __restrict__ Wv)
{
    int n = blockIdx.x;
    int which = blockIdx.y;
    const float* __restrict__ W = (which == 0) ? Wq : (which == 1) ? Wk : Wv;
    int base = which * H * D + n * D;
    for (int it = 0; it < 4; it++) {
        int k = threadIdx.x + it * 256;
        float w = W[(size_t)k * H + n];
        __nv_bfloat16 hi = __float2bfloat16(w);
        __nv_bfloat16 lo = __float2bfloat16(w - __bfloat162float(hi));
        g_bthi[base + k] = hi;
        g_btlo[base + k] = lo;
    }
}

// ============================================================
// Kernel 1: fused QKV. CTA tile 64(M) x 192(N=q|k|v), K-chunks of 64.
// ============================================================
#define QKV_BUFSZ 65536
#define QAHI(b) ((b) * QKV_BUFSZ)
#define QALO(b) ((b) * QKV_BUFSZ + 8192)
#define QBHI(b) ((b) * QKV_BUFSZ + 16384)
#define QBLO(b) ((b) * QKV_BUFSZ + 40960)

__global__ __launch_bounds__(256, 1) void qkv_mma_kernel(
    const float* __restrict__ x,
    const float* __restrict__ bq, const float* __restrict__ bk, const float* __restrict__ bv)
{
    extern __shared__ __align__(16) char sm[];
    const uint32_t smb = smem_u32(sm);

    const int tid = threadIdx.x;
    const int w = tid >> 5, l = tid & 31;
    const int wm = w & 1, wn = w >> 1;
    const int row0 = blockIdx.x * 64;

    float4 xr[2][2];
    float acc[2][6][4] = {};

    auto prefetch = [&](int c) {
        int k0 = c * 64;
        #pragma unroll
        for (int it = 0; it < 2; it++) {
            int lin = tid + it * 256;
            int r = lin >> 3, c8 = lin & 7;
            const float* src = x + (size_t)(row0 + r) * D + k0 + c8 * 8;
            xr[it][0] = *(const float4*)src;
            xr[it][1] = *(const float4*)(src + 4);
        }
    };
    auto sts_convert = [&](int buf) {
        #pragma unroll
        for (int it = 0; it < 2; it++) {
            int lin = tid + it * 256;
            int r = lin >> 3, c8 = lin & 7;
            float f[8] = {xr[it][0].x, xr[it][0].y, xr[it][0].z, xr[it][0].w,
                          xr[it][1].x, xr[it][1].y, xr[it][1].z, xr[it][1].w};
            __nv_bfloat16 hi[8], lo[8];
            #pragma unroll
            for (int u = 0; u < 8; u++) {
                hi[u] = __float2bfloat16(f[u]);
                lo[u] = __float2bfloat16(f[u] - __bfloat162float(hi[u]));
            }
            uint32_t off = swz128(r * 128 + c8 * 16);
            __nv_bfloat162 h2[4] = {{hi[0],hi[1]},{hi[2],hi[3]},{hi[4],hi[5]},{hi[6],hi[7]}};
            __nv_bfloat162 l2[4] = {{lo[0],lo[1]},{lo[2],lo[3]},{lo[4],lo[5]},{lo[6],lo[7]}};
            *(uint4*)(sm + QAHI(buf) + off) = *(uint4*)h2;
            *(uint4*)(sm + QALO(buf) + off) = *(uint4*)l2;
        }
    };
    auto issueB = [&](int c, int buf) {
        int k0 = c * 64;
        #pragma unroll
        for (int it = 0; it < 6; it++) {
            int lin = tid + it * 256;
            int r = lin >> 3, c16 = lin & 7;
            uint32_t off = swz128(r * 128 + c16 * 16);
            CP_ASYNC16(smb + QBHI(buf) + off, g_bthi + (size_t)r * D + k0 + c16 * 8);
            CP_ASYNC16(smb + QBLO(buf) + off, g_btlo + (size_t)r * D + k0 + c16 * 8);
        }
    };

    prefetch(0);
    issueB(0, 0); CP_COMMIT();

    for (int c = 0; c < 16; c++) {
        const int buf = c & 1;
        sts_convert(buf);
        if (c < 15) {
            issueB(c + 1, buf ^ 1); CP_COMMIT();
            prefetch(c + 1);
            CP_WAIT1();
        } else {
            CP_WAIT0();
        }
        __syncthreads();

        const uint32_t aHi = smb + QAHI(buf), aLo = smb + QALO(buf);
        const uint32_t bHi = smb + QBHI(buf), bLo = smb + QBLO(buf);
        #pragma unroll
        for (int ks = 0; ks < 4; ks++) {
            const int kb = ks * 32;
            uint32_t ah[2][4], al[2][4];
            #pragma unroll
            for (int t = 0; t < 2; t++) {
                int row = wm * 32 + t * 16 + (l & 7) + (l & 8);
                uint32_t off = swz128(row * 128 + kb + (l & 16));
                ldsm_x4(aHi + off, ah[t][0], ah[t][1], ah[t][2], ah[t][3]);
                ldsm_x4(aLo + off, al[t][0], al[t][1], al[t][2], al[t][3]);
            }
            uint32_t bh[3][4], bl[3][4];
            #pragma unroll
            for (int bp = 0; bp < 3; bp++) {
                int n = wn * 48 + bp * 16 + ((l & 16) >> 1) + (l & 7);
                uint32_t off = swz128(n * 128 + kb + ((l & 8) << 1));
                ldsm_x4(bHi + off, bh[bp][0], bh[bp][1], bh[bp][2], bh[bp][3]);
                ldsm_x4(bLo + off, bl[bp][0], bl[bp][1], bl[bp][2], bl[bp][3]);
            }
            #pragma unroll
            for (int t = 0; t < 2; t++)
                #pragma unroll
                for (int u = 0; u < 6; u++) {
                    int bp = u >> 1, s = (u & 1) * 2;
                    mma_bf16(acc[t][u], ah[t], bh[bp][s], bh[bp][s + 1]);
                    mma_bf16(acc[t][u], al[t], bh[bp][s], bh[bp][s + 1]);
                    mma_bf16(acc[t][u], ah[t], bl[bp][s], bl[bp][s + 1]);
                }
        }
        __syncthreads();
    }

    const int l4 = l >> 2, l2 = 2 * (l & 3);
    #pragma unroll
    for (int t = 0; t < 2; t++) {
        #pragma unroll
        for (int u = 0; u < 6; u++) {
            int r = row0 + wm * 32 + t * 16 + l4;
            int nn = wn * 48 + u * 8 + l2;
            int which = nn >> 6, col = nn & 63;
            const float* bias = (which == 0) ? bq : (which == 1) ? bk : bv;
            float b0 = bias[col], b1 = bias[col + 1];
            float v0 = acc[t][u][0] + b0, v1 = acc[t][u][1] + b1;
            float v2 = acc[t][u][2] + b0, v3 = acc[t][u][3] + b1;
            if (which == 2) {
                float2 p0 = {v0, v1}, p1 = {v2, v3};
                *(float2*)&g_v[(size_t)r * H + col] = p0;
                *(float2*)&g_v[(size_t)(r + 8) * H + col] = p1;
            } else {
                size_t off = (size_t)which * BN * H;
                __nv_bfloat16 h0 = __float2bfloat16(v0), h1 = __float2bfloat16(v1);
                __nv_bfloat16 h2 = __float2bfloat16(v2), h3 = __float2bfloat16(v3);
                *(__nv_bfloat162*)&g_qkhi[off + (size_t)r * H + col] = __nv_bfloat162(h0, h1);
                *(__nv_bfloat162*)&g_qkhi[off + (size_t)(r + 8) * H + col] = __nv_bfloat162(h2, h3);
                __nv_bfloat162 lo0(__float2bfloat16(v0 - __bfloat162float(h0)),
                                   __float2bfloat16(v1 - __bfloat162float(h1)));
                __nv_bfloat162 lo1(__float2bfloat16(v2 - __bfloat162float(h2)),
                                   __float2bfloat16(v3 - __bfloat162float(h3)));
                *(__nv_bfloat162*)&g_qklo[off + (size_t)r * H + col] = lo0;
                *(__nv_bfloat162*)&g_qklo[off + (size_t)(r + 8) * H + col] = lo1;
            }
        }
    }
}

// ============================================================
// Kernel 2: S = Q.K^T, 128x128 triangular tiles, 512 threads (4m x 4n warps).
// ============================================================
__global__ __launch_bounds__(512) void s_mma_kernel()
{
    extern __shared__ char sms[];
    const uint32_t smb = smem_u32(sms);

    int p = blockIdx.x;
    int bi = 0;
    while (p >= NB2 - bi) { p -= NB2 - bi; bi++; }
    int bj = bi + p;
    int b = blockIdx.y;

    const int tid = threadIdx.x;
    const int w = tid >> 5, l = tid & 31;
    const int wm = w & 3, wn = w >> 2;

    const __nv_bfloat16* __restrict__ src[4] = {
        g_qkhi + (size_t)(b * N + bi * 128) * H,
        g_qklo + (size_t)(b * N + bi * 128) * H,
        g_qkhi + (size_t)BN * H + (size_t)(b * N + bj * 128) * H,
        g_qklo + (size_t)BN * H + (size_t)(b * N + bj * 128) * H
    };
    #pragma unroll
    for (int tile = 0; tile < 4; tile++) {
        #pragma unroll
        for (int it = 0; it < 2; it++) {
            int lin = tid + it * 512;
            int r = lin >> 3, c16 = lin & 7;
            uint4 v = *(const uint4*)(src[tile] + (size_t)r * H + c16 * 8);
            *(uint4*)(sms + tile * 16384 + swz128(r * 128 + c16 * 16)) = v;
        }
    }
    __syncthreads();

    float acc[2][4][4] = {};
    #pragma unroll
    for (int pass = 0; pass < 3; pass++) {
        const uint32_t aBase = smb + ((pass == 1) ? 16384 : 0);
        const uint32_t bBase = smb + ((pass == 2) ? 49152 : 32768);
        #pragma unroll
        for (int ks = 0; ks < 4; ks++) {
            const int kb = ks * 32;
            uint32_t a[2][4];
            #pragma unroll
            for (int t = 0; t < 2; t++) {
                int row = wm * 32 + t * 16 + (l & 7) + (l & 8);
                ldsm_x4(aBase + swz128(row * 128 + kb + (l & 16)), a[t][0], a[t][1], a[t][2], a[t][3]);
            }
            uint32_t bfr[2][4];
            #pragma unroll
            for (int bp = 0; bp < 2; bp++) {
                int n = wn * 32 + bp * 16 + ((l & 16) >> 1) + (l & 7);
                ldsm_x4(bBase + swz128(n * 128 + kb + ((l & 8) << 1)),
                        bfr[bp][0], bfr[bp][1], bfr[bp][2], bfr[bp][3]);
            }
            #pragma unroll
            for (int t = 0; t < 2; t++)
                #pragma unroll
                for (int u = 0; u < 4; u++)
                    mma_bf16(acc[t][u], a[t], bfr[u >> 1][(u & 1) * 2], bfr[u >> 1][(u & 1) * 2 + 1]);
        }
    }

    const int l4 = l >> 2, l2 = 2 * (l & 3);
    #pragma unroll
    for (int t = 0; t < 2; t++) {
        #pragma unroll
        for (int u = 0; u < 4; u++) {
            int i = bi * 128 + wm * 32 + t * 16 + l4;
            int j = bj * 128 + wn * 32 + u * 8 + l2;
            float2 p0 = {acc[t][u][0], acc[t][u][1]};
            float2 p1 = {acc[t][u][2], acc[t][u][3]};
            *(float2*)&g_S[((size_t)(b * N + i)) * N + j] = p0;
            *(float2*)&g_S[((size_t)(b * N + i + 8)) * N + j] = p1;
        }
    }
}

// ============================================================
// Kernel 3: per-j-row softmax. Minimal-ALU version:
//   t = s*C at load (C = SCALE*log2e); invalid lanes get -inf;
//   causal mask only touches warp 0 (first 128 cols);
//   e = ex2(t - m); shfl reductions; fused v' = linv*v.
// ============================================================
__global__ __launch_bounds__(256) void ep_kernel()
{
    const int row = blockIdx.x;            // b*N + j
    const int j = row & (N - 1);
    const int i0 = j & ~127;               // av only reads i >= this
    const int L = N - i0;                  // 128..2048, multiple of 128
    const int jrel = j - i0;               // 0..127
    const float* __restrict__ base = g_S + (size_t)row * N + i0;
    const int tid = threadIdx.x;
    const int w = tid >> 5, l = tid & 31;
    const float C = 0.18033688011112042f;  // 0.125 * log2(e)
    const float NEG = -INFINITY;

    float t[8];
    const int ib0 = tid * 4, ib1 = tid * 4 + 1024;
    if (ib0 < L) {
        float4 v = *(const float4*)&base[ib0];
        t[0] = v.x * C; t[1] = v.y * C; t[2] = v.z * C; t[3] = v.w * C;
    } else { t[0] = t[1] = t[2] = t[3] = NEG; }
    if (ib1 < L) {
        float4 v = *(const float4*)&base[ib1];
        t[4] = v.x * C; t[5] = v.y * C; t[6] = v.z * C; t[7] = v.w * C;
    } else { t[4] = t[5] = t[6] = t[7] = NEG; }

    if (tid < 32) {                        // causal mask lives entirely in warp 0
        #pragma unroll
        for (int u = 0; u < 4; u++)
            if (ib0 + u < jrel) t[u] = NEG;
    }

    // block max: register -> warp shfl -> 8-wide smem
    __shared__ float smax[8], ssum[8];
    float m = t[0];
    #pragma unroll
    for (int u = 1; u < 8; u++) m = fmaxf(m, t[u]);
    #pragma unroll
    for (int o = 16; o > 0; o >>= 1) m = fmaxf(m, __shfl_xor_sync(0xFFFFFFFFu, m, o));
    if (l == 0) smax[w] = m;
    __syncthreads();
    m = smax[0];
    #pragma unroll
    for (int u = 1; u < 8; u++) m = fmaxf(m, smax[u]);

    // exp + sum (masked lanes: ex2(-inf) = 0)
    float e[8];
    float ls = 0.0f;
    #pragma unroll
    for (int u = 0; u < 8; u++) { e[u] = ex2f(t[u] - m); ls += e[u]; }
    #pragma unroll
    for (int o = 16; o > 0; o >>= 1) ls += __shfl_xor_sync(0xFFFFFFFFu, ls, o);
    if (l == 0) ssum[w] = ls;
    __syncthreads();
    float tot = ssum[0];
    #pragma unroll
    for (int u = 1; u < 8; u++) tot += ssum[u];
    const float linv = 1.0f / tot;

    // write E (fp16)
    if (ib0 < L) {
        __half2 p01 = __floats2half2_rn(e[0], e[1]);
        __half2 p23 = __floats2half2_rn(e[2], e[3]);
        uint2 wo = {*(uint32_t*)&p01, *(uint32_t*)&p23};
        *(uint2*)&g_E[(size_t)row * N + i0 + ib0] = wo;
    }
    if (ib1 < L) {
        __half2 p45 = __floats2half2_rn(e[4], e[5]);
        __half2 p67 = __floats2half2_rn(e[6], e[7]);
        uint2 wo = {*(uint32_t*)&p45, *(uint32_t*)&p67};
        *(uint2*)&g_E[(size_t)row * N + i0 + ib1] = wo;
    }

    // fused v scaling: v'[j] = linv * v[j], fp16 hi/lo
    if (tid < 16) {
        float4 v = *(const float4*)&g_v[(size_t)row * H + tid * 4];
        float f[4] = {v.x * linv, v.y * linv, v.z * linv, v.w * linv};
        __half hi[4], lo[4];
        #pragma unroll
        for (int u = 0; u < 4; u++) {
            hi[u] = __float2half(f[u]);
            lo[u] = __float2half(f[u] - __half2float(hi[u]));
        }
        __half2 h01(hi[0], hi[1]), h23(hi[2], hi[3]);
        __half2 l01(lo[0], lo[1]), l23(lo[2], lo[3]);
        uint2 wh = {*(uint32_t*)&h01, *(uint32_t*)&h23};
        uint2 wl = {*(uint32_t*)&l01, *(uint32_t*)&l23};
        *(uint2*)&g_vhi[(size_t)row * H + tid * 4] = wh;
        *(uint2*)&g_vlo[(size_t)row * H + tid * 4] = wl;
    }
}

// ============================================================
// Kernel 4: AV partials via fp16 mma, 512 threads (4i x 4h warps, warp 32x16).
// ============================================================
__global__ __launch_bounds__(512) void av_mma_kernel()
{
    int p = blockIdx.x, b = blockIdx.y;
    int bi = 0;
    for (;;) {
        int nc = ((2 * bi + 1) >> 2) + 1;
        if (p < nc) break;
        p -= nc; bi++;
    }
    int chunk = p;
    int i0 = bi * 128;
    int jb0 = chunk * 4;
    int jb_end = min(jb0 + 4, 2 * bi + 2);

    __shared__ __align__(16) char smE[16384];
    __shared__ __align__(16) char smVh[8192];
    __shared__ __align__(16) char smVl[8192];
    const uint32_t eb = smem_u32(smE), vhb = smem_u32(smVh), vlb = smem_u32(smVl);

    int tid = threadIdx.x;
    int w = tid >> 5, l = tid & 31;
    int im = w & 3, ih = w >> 2;

    float acc[2][2][4] = {};

    for (int jb = jb0; jb < jb_end; jb++) {
        int j0 = jb * 64;
        __syncthreads();
        #pragma unroll
        for (int it = 0; it < 2; it++) {
            int lin = tid + it * 512;
            int jr = lin >> 4, c16 = lin & 15;
            int half = c16 >> 3, ic16 = c16 & 7;
            uint4 t = *(const uint4*)&g_E[((size_t)b * N + j0 + jr) * N + i0 + c16 * 8];
            *(uint4*)(smE + half * 8192 + swz128(jr * 128 + ic16 * 16)) = t;
        }
        {
            int jr = tid >> 3, c16 = tid & 7;
            uint4 th = *(const uint4*)&g_vhi[((size_t)b * N + j0 + jr) * H + c16 * 8];
            uint4 tl = *(const uint4*)&g_vlo[((size_t)b * N + j0 + jr) * H + c16 * 8];
            uint32_t off = swz128(jr * 128 + c16 * 16);
            *(uint4*)(smVh + off) = th;
            *(uint4*)(smVl + off) = tl;
        }
        __syncthreads();

        #pragma unroll
        for (int ks = 0; ks < 4; ks++) {
            uint32_t a[2][4];
            #pragma unroll
            for (int t = 0; t < 2; t++) {
                int il = im * 32 + t * 16;
                int half = il >> 6, iin = il & 63;
                int jr = ks * 16 + (l & 7) + ((l & 16) >> 1);
                int ic = iin + (l & 8);
                ldsm_x4_t(eb + half * 8192 + swz128(jr * 128 + ic * 2),
                          a[t][0], a[t][1], a[t][2], a[t][3]);
            }
            uint32_t bh[4], bl[4];
            {
                int jrb = ks * 16 + (l & 7) + (l & 8);
                int hc = ih * 16 + ((l & 16) >> 1);
                uint32_t off = swz128(jrb * 128 + hc * 2);
                ldsm_x4_t(vhb + off, bh[0], bh[1], bh[2], bh[3]);
                ldsm_x4_t(vlb + off, bl[0], bl[1], bl[2], bl[3]);
            }
            #pragma unroll
            for (int t = 0; t < 2; t++)
                #pragma unroll
                for (int n8 = 0; n8 < 2; n8++) {
                    mma_fp16(acc[t][n8], a[t], bh[2 * n8], bh[2 * n8 + 1]);
                    mma_fp16(acc[t][n8], a[t], bl[2 * n8], bl[2 * n8 + 1]);
                }
        }
    }

    const int l4 = l >> 2, l2 = 2 * (l & 3);
    #pragma unroll
    for (int t = 0; t < 2; t++) {
        #pragma unroll
        for (int n8 = 0; n8 < 2; n8++) {
            int i = i0 + im * 32 + t * 16 + l4;
            int h = ih * 16 + n8 * 8 + l2;
            float2 p0 = {acc[t][n8][0], acc[t][n8][1]};
            float2 p1 = {acc[t][n8][2], acc[t][n8][3]};
            *(float2*)&g_part[((size_t)chunk * BN + b * N + i) * H + h] = p0;
            *(float2*)&g_part[((size_t)chunk * BN + b * N + i + 8) * H + h] = p1;
        }
    }
}

// ============================================================
// Kernel 5: reduce partial chunks
// ============================================================
__global__ __launch_bounds__(256) void reduce_kernel(float* __restrict__ out)
{
    int idx = blockIdx.x * 256 + threadIdx.x;
    if (idx >= BN * H) return;
    int row = idx / H;
    int i = row & (N - 1);
    int nch = (i >> 8) + 1;
    float s = 0.0f;
    for (int c = 0; c < nch; c++)
        s += g_part[(size_t)c * BN * H + idx];
    out[idx] = s;
}

// ============================================================
extern "C" void kernel_launch(void* const* d_in, const int* in_sizes, int n_in,
                              void* d_out, int out_size)
{
    const float* x  = (const float*)d_in[0];
    const float* Wq = (const float*)d_in[1];
    const float* bq = (const float*)d_in[2];
    const float* Wk = (const float*)d_in[3];
    const float* bk = (const float*)d_in[4];
    const float* Wv = (const float*)d_in[5];
    const float* bv = (const float*)d_in[6];
    float* out = (float*)d_out;

    cudaFuncSetAttribute(qkv_mma_kernel, cudaFuncAttributeMaxDynamicSharedMemorySize, 2 * QKV_BUFSZ);
    cudaFuncSetAttribute(s_mma_kernel, cudaFuncAttributeMaxDynamicSharedMemorySize, 65536);

    convert_w_kernel<<<dim3(H, 3), 256>>>(Wq, Wk, Wv);
    qkv_mma_kernel<<<BN / 64, 256, 2 * QKV_BUFSZ>>>(x, bq, bk, bv);
    s_mma_kernel<<<dim3(NPAIR2, B), 512, 65536>>>();
    ep_kernel<<<BN, 256>>>();
    av_mma_kernel<<<dim3(72, B), 512>>>();
    reduce_kernel<<<(BN * H + 255) / 256, 256>>>(out);
}

// round 15
// speedup vs baseline: 2.8345x; 1.0550x over previous
#include <cuda_runtime.h>
#include <cuda_bf16.h>
#include <cuda_fp16.h>
#include <math.h>
#include <stdint.h>

#define B 4
#define N 2048
#define D 1024
#define H 64
#define BN (B*N)            // 8192
#define SCALE 0.125f
#define CLOG2E 0.18033688011112042f   // SCALE * log2(e)
#define NB2 16              // N/128
#define NPAIR2 (NB2*(NB2+1)/2)   // 136
#define NCHUNK 8

// ---- scratch (device globals) ----
__device__ __nv_bfloat16 g_bthi[3*H*D];   // [which*64+n][k] transposed weights, hi
__device__ __nv_bfloat16 g_btlo[3*H*D];
__device__ __nv_bfloat16 g_qkhi[2*BN*H];  // q,k bf16 hi ([row][64])
__device__ __nv_bfloat16 g_qklo[2*BN*H];
__device__ float g_v[BN*H];
__device__ float g_S[(size_t)B*N*N];      // holds t = score * SCALE * log2(e)
__device__ __half g_E[(size_t)B*N*N];     // unnormalized exp, [b][j][i]
__device__ __half g_vhi[BN*H];            // v * linv, fp16 hi
__device__ __half g_vlo[BN*H];
__device__ float g_part[(size_t)NCHUNK*BN*H];

// ============================================================
// helpers
// ============================================================
__device__ __forceinline__ uint32_t smem_u32(const void* p) {
    uint32_t a;
    asm("{ .reg .u64 t; cvta.to.shared.u64 t, %1; cvt.u32.u64 %0, t; }" : "=r"(a) : "l"(p));
    return a;
}
static __device__ __forceinline__ uint32_t swz128(uint32_t off) { return off ^ ((off >> 3) & 0x70); }

__device__ __forceinline__ float ex2f(float x) {
    float r;
    asm("ex2.approx.ftz.f32 %0, %1;" : "=f"(r) : "f"(x));
    return r;
}

__device__ __forceinline__ void ldsm_x4(uint32_t addr, uint32_t& r0, uint32_t& r1, uint32_t& r2, uint32_t& r3) {
    asm volatile("ldmatrix.sync.aligned.m8n8.x4.shared.b16 {%0,%1,%2,%3}, [%4];"
                 : "=r"(r0), "=r"(r1), "=r"(r2), "=r"(r3) : "r"(addr));
}
__device__ __forceinline__ void ldsm_x4_t(uint32_t addr, uint32_t& r0, uint32_t& r1, uint32_t& r2, uint32_t& r3) {
    asm volatile("ldmatrix.sync.aligned.m8n8.x4.trans.shared.b16 {%0,%1,%2,%3}, [%4];"
                 : "=r"(r0), "=r"(r1), "=r"(r2), "=r"(r3) : "r"(addr));
}
__device__ __forceinline__ void mma_bf16(float* c, const uint32_t* a, uint32_t b0, uint32_t b1) {
    asm volatile("mma.sync.aligned.m16n8k16.row.col.f32.bf16.bf16.f32 "
                 "{%0,%1,%2,%3}, {%4,%5,%6,%7}, {%8,%9}, {%0,%1,%2,%3};"
                 : "+f"(c[0]), "+f"(c[1]), "+f"(c[2]), "+f"(c[3])
                 : "r"(a[0]), "r"(a[1]), "r"(a[2]), "r"(a[3]), "r"(b0), "r"(b1));
}
__device__ __forceinline__ void mma_fp16(float* c, const uint32_t* a, uint32_t b0, uint32_t b1) {
    asm volatile("mma.sync.aligned.m16n8k16.row.col.f32.f16.f16.f32 "
                 "{%0,%1,%2,%3}, {%4,%5,%6,%7}, {%8,%9}, {%0,%1,%2,%3};"
                 : "+f"(c[0]), "+f"(c[1]), "+f"(c[2]), "+f"(c[3])
                 : "r"(a[0]), "r"(a[1]), "r"(a[2]), "r"(a[3]), "r"(b0), "r"(b1));
}
#define CP_ASYNC16(dst, src) asm volatile("cp.async.cg.shared.global [%0], [%1], 16;" :: "r"(dst), "l"(src))
#define CP_COMMIT() asm volatile("cp.async.commit_group;" ::: "memory")
#define CP_WAIT1() asm volatile("cp.async.wait_group 1;" ::: "memory")
#define CP_WAIT0() asm volatile("cp.async.wait_group 0;" ::: "memory")

// ============================================================
// Kernel 0: transpose+split W -> [which*64+n][k], hi/lo
// ============================================================
__global__ __launch_bounds__(256) void convert_w_kernel(
    const float* __restrict__ Wq, const float* __restrict__ Wk, const float* __restrict__ Wv)
{
    int n = blockIdx.x;
    int which = blockIdx.y;
    const float* __restrict__ W = (which == 0) ? Wq : (which == 1) ? Wk : Wv;
    int base = which * H * D + n * D;
    for (int it = 0; it < 4; it++) {
        int k = threadIdx.x + it * 256;
        float w = W[(size_t)k * H + n];
        __nv_bfloat16 hi = __float2bfloat16(w);
        __nv_bfloat16 lo = __float2bfloat16(w - __bfloat162float(hi));
        g_bthi[base + k] = hi;
        g_btlo[base + k] = lo;
    }
}

// ============================================================
// Kernel 1: fused QKV. CTA tile 64(M) x 192(N=q|k|v), K-chunks of 64.
// ============================================================
#define QKV_BUFSZ 65536
#define QAHI(b) ((b) * QKV_BUFSZ)
#define QALO(b) ((b) * QKV_BUFSZ + 8192)
#define QBHI(b) ((b) * QKV_BUFSZ + 16384)
#define QBLO(b) ((b) * QKV_BUFSZ + 40960)

__global__ __launch_bounds__(256, 1) void qkv_mma_kernel(
    const float* __restrict__ x,
    const float* __restrict__ bq, const float* __restrict__ bk, const float* __restrict__ bv)
{
    extern __shared__ __align__(16) char sm[];
    const uint32_t smb = smem_u32(sm);

    const int tid = threadIdx.x;
    const int w = tid >> 5, l = tid & 31;
    const int wm = w & 1, wn = w >> 1;
    const int row0 = blockIdx.x * 64;

    float4 xr[2][2];
    float acc[2][6][4] = {};

    auto prefetch = [&](int c) {
        int k0 = c * 64;
        #pragma unroll
        for (int it = 0; it < 2; it++) {
            int lin = tid + it * 256;
            int r = lin >> 3, c8 = lin & 7;
            const float* src = x + (size_t)(row0 + r) * D + k0 + c8 * 8;
            xr[it][0] = *(const float4*)src;
            xr[it][1] = *(const float4*)(src + 4);
        }
    };
    auto sts_convert = [&](int buf) {
        #pragma unroll
        for (int it = 0; it < 2; it++) {
            int lin = tid + it * 256;
            int r = lin >> 3, c8 = lin & 7;
            float f[8] = {xr[it][0].x, xr[it][0].y, xr[it][0].z, xr[it][0].w,
                          xr[it][1].x, xr[it][1].y, xr[it][1].z, xr[it][1].w};
            __nv_bfloat16 hi[8], lo[8];
            #pragma unroll
            for (int u = 0; u < 8; u++) {
                hi[u] = __float2bfloat16(f[u]);
                lo[u] = __float2bfloat16(f[u] - __bfloat162float(hi[u]));
            }
            uint32_t off = swz128(r * 128 + c8 * 16);
            __nv_bfloat162 h2[4] = {{hi[0],hi[1]},{hi[2],hi[3]},{hi[4],hi[5]},{hi[6],hi[7]}};
            __nv_bfloat162 l2[4] = {{lo[0],lo[1]},{lo[2],lo[3]},{lo[4],lo[5]},{lo[6],lo[7]}};
            *(uint4*)(sm + QAHI(buf) + off) = *(uint4*)h2;
            *(uint4*)(sm + QALO(buf) + off) = *(uint4*)l2;
        }
    };
    auto issueB = [&](int c, int buf) {
        int k0 = c * 64;
        #pragma unroll
        for (int it = 0; it < 6; it++) {
            int lin = tid + it * 256;
            int r = lin >> 3, c16 = lin & 7;
            uint32_t off = swz128(r * 128 + c16 * 16);
            CP_ASYNC16(smb + QBHI(buf) + off, g_bthi + (size_t)r * D + k0 + c16 * 8);
            CP_ASYNC16(smb + QBLO(buf) + off, g_btlo + (size_t)r * D + k0 + c16 * 8);
        }
    };

    prefetch(0);
    issueB(0, 0); CP_COMMIT();

    for (int c = 0; c < 16; c++) {
        const int buf = c & 1;
        sts_convert(buf);
        if (c < 15) {
            issueB(c + 1, buf ^ 1); CP_COMMIT();
            prefetch(c + 1);
            CP_WAIT1();
        } else {
            CP_WAIT0();
        }
        __syncthreads();

        const uint32_t aHi = smb + QAHI(buf), aLo = smb + QALO(buf);
        const uint32_t bHi = smb + QBHI(buf), bLo = smb + QBLO(buf);
        #pragma unroll
        for (int ks = 0; ks < 4; ks++) {
            const int kb = ks * 32;
            uint32_t ah[2][4], al[2][4];
            #pragma unroll
            for (int t = 0; t < 2; t++) {
                int row = wm * 32 + t * 16 + (l & 7) + (l & 8);
                uint32_t off = swz128(row * 128 + kb + (l & 16));
                ldsm_x4(aHi + off, ah[t][0], ah[t][1], ah[t][2], ah[t][3]);
                ldsm_x4(aLo + off, al[t][0], al[t][1], al[t][2], al[t][3]);
            }
            uint32_t bh[3][4], bl[3][4];
            #pragma unroll
            for (int bp = 0; bp < 3; bp++) {
                int n = wn * 48 + bp * 16 + ((l & 16) >> 1) + (l & 7);
                uint32_t off = swz128(n * 128 + kb + ((l & 8) << 1));
                ldsm_x4(bHi + off, bh[bp][0], bh[bp][1], bh[bp][2], bh[bp][3]);
                ldsm_x4(bLo + off, bl[bp][0], bl[bp][1], bl[bp][2], bl[bp][3]);
            }
            #pragma unroll
            for (int t = 0; t < 2; t++)
                #pragma unroll
                for (int u = 0; u < 6; u++) {
                    int bp = u >> 1, s = (u & 1) * 2;
                    mma_bf16(acc[t][u], ah[t], bh[bp][s], bh[bp][s + 1]);
                    mma_bf16(acc[t][u], al[t], bh[bp][s], bh[bp][s + 1]);
                    mma_bf16(acc[t][u], ah[t], bl[bp][s], bl[bp][s + 1]);
                }
        }
        __syncthreads();
    }

    const int l4 = l >> 2, l2 = 2 * (l & 3);
    #pragma unroll
    for (int t = 0; t < 2; t++) {
        #pragma unroll
        for (int u = 0; u < 6; u++) {
            int r = row0 + wm * 32 + t * 16 + l4;
            int nn = wn * 48 + u * 8 + l2;
            int which = nn >> 6, col = nn & 63;
            const float* bias = (which == 0) ? bq : (which == 1) ? bk : bv;
            float b0 = bias[col], b1 = bias[col + 1];
            float v0 = acc[t][u][0] + b0, v1 = acc[t][u][1] + b1;
            float v2 = acc[t][u][2] + b0, v3 = acc[t][u][3] + b1;
            if (which == 2) {
                float2 p0 = {v0, v1}, p1 = {v2, v3};
                *(float2*)&g_v[(size_t)r * H + col] = p0;
                *(float2*)&g_v[(size_t)(r + 8) * H + col] = p1;
            } else {
                size_t off = (size_t)which * BN * H;
                __nv_bfloat16 h0 = __float2bfloat16(v0), h1 = __float2bfloat16(v1);
                __nv_bfloat16 h2 = __float2bfloat16(v2), h3 = __float2bfloat16(v3);
                *(__nv_bfloat162*)&g_qkhi[off + (size_t)r * H + col] = __nv_bfloat162(h0, h1);
                *(__nv_bfloat162*)&g_qkhi[off + (size_t)(r + 8) * H + col] = __nv_bfloat162(h2, h3);
                __nv_bfloat162 lo0(__float2bfloat16(v0 - __bfloat162float(h0)),
                                   __float2bfloat16(v1 - __bfloat162float(h1)));
                __nv_bfloat162 lo1(__float2bfloat16(v2 - __bfloat162float(h2)),
                                   __float2bfloat16(v3 - __bfloat162float(h3)));
                *(__nv_bfloat162*)&g_qklo[off + (size_t)r * H + col] = lo0;
                *(__nv_bfloat162*)&g_qklo[off + (size_t)(r + 8) * H + col] = lo1;
            }
        }
    }
}

// ============================================================
// Kernel 2: S = Q.K^T (x SCALE*log2e), 128x128 triangular tiles, 512 threads.
// ============================================================
__global__ __launch_bounds__(512) void s_mma_kernel()
{
    extern __shared__ char sms[];
    const uint32_t smb = smem_u32(sms);

    int p = blockIdx.x;
    int bi = 0;
    while (p >= NB2 - bi) { p -= NB2 - bi; bi++; }
    int bj = bi + p;
    int b = blockIdx.y;

    const int tid = threadIdx.x;
    const int w = tid >> 5, l = tid & 31;
    const int wm = w & 3, wn = w >> 2;

    const __nv_bfloat16* __restrict__ src[4] = {
        g_qkhi + (size_t)(b * N + bi * 128) * H,
        g_qklo + (size_t)(b * N + bi * 128) * H,
        g_qkhi + (size_t)BN * H + (size_t)(b * N + bj * 128) * H,
        g_qklo + (size_t)BN * H + (size_t)(b * N + bj * 128) * H
    };
    #pragma unroll
    for (int tile = 0; tile < 4; tile++) {
        #pragma unroll
        for (int it = 0; it < 2; it++) {
            int lin = tid + it * 512;
            int r = lin >> 3, c16 = lin & 7;
            uint4 v = *(const uint4*)(src[tile] + (size_t)r * H + c16 * 8);
            *(uint4*)(sms + tile * 16384 + swz128(r * 128 + c16 * 16)) = v;
        }
    }
    __syncthreads();

    float acc[2][4][4] = {};
    #pragma unroll
    for (int pass = 0; pass < 3; pass++) {
        const uint32_t aBase = smb + ((pass == 1) ? 16384 : 0);
        const uint32_t bBase = smb + ((pass == 2) ? 49152 : 32768);
        #pragma unroll
        for (int ks = 0; ks < 4; ks++) {
            const int kb = ks * 32;
            uint32_t a[2][4];
            #pragma unroll
            for (int t = 0; t < 2; t++) {
                int row = wm * 32 + t * 16 + (l & 7) + (l & 8);
                ldsm_x4(aBase + swz128(row * 128 + kb + (l & 16)), a[t][0], a[t][1], a[t][2], a[t][3]);
            }
            uint32_t bfr[2][4];
            #pragma unroll
            for (int bp = 0; bp < 2; bp++) {
                int n = wn * 32 + bp * 16 + ((l & 16) >> 1) + (l & 7);
                ldsm_x4(bBase + swz128(n * 128 + kb + ((l & 8) << 1)),
                        bfr[bp][0], bfr[bp][1], bfr[bp][2], bfr[bp][3]);
            }
            #pragma unroll
            for (int t = 0; t < 2; t++)
                #pragma unroll
                for (int u = 0; u < 4; u++)
                    mma_bf16(acc[t][u], a[t], bfr[u >> 1][(u & 1) * 2], bfr[u >> 1][(u & 1) * 2 + 1]);
        }
    }

    const int l4 = l >> 2, l2 = 2 * (l & 3);
    #pragma unroll
    for (int t = 0; t < 2; t++) {
        #pragma unroll
        for (int u = 0; u < 4; u++) {
            int i = bi * 128 + wm * 32 + t * 16 + l4;
            int j = bj * 128 + wn * 32 + u * 8 + l2;
            float2 p0 = {acc[t][u][0] * CLOG2E, acc[t][u][1] * CLOG2E};
            float2 p1 = {acc[t][u][2] * CLOG2E, acc[t][u][3] * CLOG2E};
            *(float2*)&g_S[((size_t)(b * N + i)) * N + j] = p0;
            *(float2*)&g_S[((size_t)(b * N + i + 8)) * N + j] = p1;
        }
    }
}

// ============================================================
// Kernel 3: per-j-row softmax. 4 rows per block (4-aligned => same strip),
// 64 threads (2 warps) per row, 8 float4 slots/thread (MLP up to 8).
// S already holds t = score*SCALE*log2e. e = ex2(t - m).
// ============================================================
__global__ __launch_bounds__(256) void ep_kernel()
{
    const int sub = threadIdx.x >> 6;          // row within group (0..3)
    const int t64 = threadIdx.x & 63;
    const int lane = threadIdx.x & 31;
    const int wh = (threadIdx.x >> 5) & 1;     // warp within 64-thread group
    const int row = blockIdx.x * 4 + sub;      // b*N + j
    const int j = row & (N - 1);
    const int i0 = j & ~127;                   // av only reads i >= this
    const int L = N - i0;                      // 128..2048
    const int jrel = j - i0;                   // 0..127
    const float* __restrict__ base = g_S + (size_t)row * N + i0;
    const float NEG = -INFINITY;

    float t[32];
    #pragma unroll
    for (int s = 0; s < 8; s++) {
        int e0 = s * 256 + t64 * 4;
        if (e0 < L) {
            float4 v = *(const float4*)&base[e0];
            t[s*4+0] = v.x; t[s*4+1] = v.y; t[s*4+2] = v.z; t[s*4+3] = v.w;
        } else {
            t[s*4+0] = t[s*4+1] = t[s*4+2] = t[s*4+3] = NEG;
        }
    }
    // causal mask: elements < jrel (slot 0 only, t64 < 32)
    if (t64 * 4 < jrel) {
        #pragma unroll
        for (int u = 0; u < 4; u++)
            if (t64 * 4 + u < jrel) t[u] = NEG;
    }

    // row max: regs -> warp shfl -> 2-warp smem combine
    __shared__ float sm2[4][2], ss2[4][2];
    float m = t[0];
    #pragma unroll
    for (int s = 1; s < 32; s++) m = fmaxf(m, t[s]);
    #pragma unroll
    for (int o = 16; o > 0; o >>= 1) m = fmaxf(m, __shfl_xor_sync(0xFFFFFFFFu, m, o));
    if (lane == 0) sm2[sub][wh] = m;
    __syncthreads();
    m = fmaxf(sm2[sub][0], sm2[sub][1]);

    // exp + sum
    float ls = 0.0f;
    #pragma unroll
    for (int s = 0; s < 32; s++) { t[s] = ex2f(t[s] - m); ls += t[s]; }
    #pragma unroll
    for (int o = 16; o > 0; o >>= 1) ls += __shfl_xor_sync(0xFFFFFFFFu, ls, o);
    if (lane == 0) ss2[sub][wh] = ls;
    __syncthreads();
    const float linv = 1.0f / (ss2[sub][0] + ss2[sub][1]);

    // write E (fp16)
    #pragma unroll
    for (int s = 0; s < 8; s++) {
        int e0 = s * 256 + t64 * 4;
        if (e0 < L) {
            __half2 p01 = __floats2half2_rn(t[s*4+0], t[s*4+1]);
            __half2 p23 = __floats2half2_rn(t[s*4+2], t[s*4+3]);
            uint2 wo = {*(uint32_t*)&p01, *(uint32_t*)&p23};
            *(uint2*)&g_E[(size_t)row * N + i0 + e0] = wo;
        }
    }

    // fused v scaling: v'[j] = linv * v[j], fp16 hi/lo
    if (t64 < 16) {
        float4 v = *(const float4*)&g_v[(size_t)row * H + t64 * 4];
        float f[4] = {v.x * linv, v.y * linv, v.z * linv, v.w * linv};
        __half hi[4], lo[4];
        #pragma unroll
        for (int u = 0; u < 4; u++) {
            hi[u] = __float2half(f[u]);
            lo[u] = __float2half(f[u] - __half2float(hi[u]));
        }
        __half2 h01(hi[0], hi[1]), h23(hi[2], hi[3]);
        __half2 l01(lo[0], lo[1]), l23(lo[2], lo[3]);
        uint2 wha = {*(uint32_t*)&h01, *(uint32_t*)&h23};
        uint2 wla = {*(uint32_t*)&l01, *(uint32_t*)&l23};
        *(uint2*)&g_vhi[(size_t)row * H + t64 * 4] = wha;
        *(uint2*)&g_vlo[(size_t)row * H + t64 * 4] = wla;
    }
}

// ============================================================
// Kernel 4: AV partials via fp16 mma, 512 threads (4i x 4h warps, warp 32x16).
// ============================================================
__global__ __launch_bounds__(512) void av_mma_kernel()
{
    int p = blockIdx.x, b = blockIdx.y;
    int bi = 0;
    for (;;) {
        int nc = ((2 * bi + 1) >> 2) + 1;
        if (p < nc) break;
        p -= nc; bi++;
    }
    int chunk = p;
    int i0 = bi * 128;
    int jb0 = chunk * 4;
    int jb_end = min(jb0 + 4, 2 * bi + 2);

    __shared__ __align__(16) char smE[16384];
    __shared__ __align__(16) char smVh[8192];
    __shared__ __align__(16) char smVl[8192];
    const uint32_t eb = smem_u32(smE), vhb = smem_u32(smVh), vlb = smem_u32(smVl);

    int tid = threadIdx.x;
    int w = tid >> 5, l = tid & 31;
    int im = w & 3, ih = w >> 2;

    float acc[2][2][4] = {};

    for (int jb = jb0; jb < jb_end; jb++) {
        int j0 = jb * 64;
        __syncthreads();
        #pragma unroll
        for (int it = 0; it < 2; it++) {
            int lin = tid + it * 512;
            int jr = lin >> 4, c16 = lin & 15;
            int half = c16 >> 3, ic16 = c16 & 7;
            uint4 t = *(const uint4*)&g_E[((size_t)b * N + j0 + jr) * N + i0 + c16 * 8];
            *(uint4*)(smE + half * 8192 + swz128(jr * 128 + ic16 * 16)) = t;
        }
        {
            int jr = tid >> 3, c16 = tid & 7;
            uint4 th = *(const uint4*)&g_vhi[((size_t)b * N + j0 + jr) * H + c16 * 8];
            uint4 tl = *(const uint4*)&g_vlo[((size_t)b * N + j0 + jr) * H + c16 * 8];
            uint32_t off = swz128(jr * 128 + c16 * 16);
            *(uint4*)(smVh + off) = th;
            *(uint4*)(smVl + off) = tl;
        }
        __syncthreads();

        #pragma unroll
        for (int ks = 0; ks < 4; ks++) {
            uint32_t a[2][4];
            #pragma unroll
            for (int t = 0; t < 2; t++) {
                int il = im * 32 + t * 16;
                int half = il >> 6, iin = il & 63;
                int jr = ks * 16 + (l & 7) + ((l & 16) >> 1);
                int ic = iin + (l & 8);
                ldsm_x4_t(eb + half * 8192 + swz128(jr * 128 + ic * 2),
                          a[t][0], a[t][1], a[t][2], a[t][3]);
            }
            uint32_t bh[4], bl[4];
            {
                int jrb = ks * 16 + (l & 7) + (l & 8);
                int hc = ih * 16 + ((l & 16) >> 1);
                uint32_t off = swz128(jrb * 128 + hc * 2);
                ldsm_x4_t(vhb + off, bh[0], bh[1], bh[2], bh[3]);
                ldsm_x4_t(vlb + off, bl[0], bl[1], bl[2], bl[3]);
            }
            #pragma unroll
            for (int t = 0; t < 2; t++)
                #pragma unroll
                for (int n8 = 0; n8 < 2; n8++) {
                    mma_fp16(acc[t][n8], a[t], bh[2 * n8], bh[2 * n8 + 1]);
                    mma_fp16(acc[t][n8], a[t], bl[2 * n8], bl[2 * n8 + 1]);
                }
        }
    }

    const int l4 = l >> 2, l2 = 2 * (l & 3);
    #pragma unroll
    for (int t = 0; t < 2; t++) {
        #pragma unroll
        for (int n8 = 0; n8 < 2; n8++) {
            int i = i0 + im * 32 + t * 16 + l4;
            int h = ih * 16 + n8 * 8 + l2;
            float2 p0 = {acc[t][n8][0], acc[t][n8][1]};
            float2 p1 = {acc[t][n8][2], acc[t][n8][3]};
            *(float2*)&g_part[((size_t)chunk * BN + b * N + i) * H + h] = p0;
            *(float2*)&g_part[((size_t)chunk * BN + b * N + i + 8) * H + h] = p1;
        }
    }
}

// ============================================================
// Kernel 5: reduce partial chunks
// ============================================================
__global__ __launch_bounds__(256) void reduce_kernel(float* __restrict__ out)
{
    int idx = blockIdx.x * 256 + threadIdx.x;
    if (idx >= BN * H) return;
    int row = idx / H;
    int i = row & (N - 1);
    int nch = (i >> 8) + 1;
    float s = 0.0f;
    for (int c = 0; c < nch; c++)
        s += g_part[(size_t)c * BN * H + idx];
    out[idx] = s;
}

// ============================================================
extern "C" void kernel_launch(void* const* d_in, const int* in_sizes, int n_in,
                              void* d_out, int out_size)
{
    const float* x  = (const float*)d_in[0];
    const float* Wq = (const float*)d_in[1];
    const float* bq = (const float*)d_in[2];
    const float* Wk = (const float*)d_in[3];
    const float* bk = (const float*)d_in[4];
    const float* Wv = (const float*)d_in[5];
    const float* bv = (const float*)d_in[6];
    float* out = (float*)d_out;

    cudaFuncSetAttribute(qkv_mma_kernel, cudaFuncAttributeMaxDynamicSharedMemorySize, 2 * QKV_BUFSZ);
    cudaFuncSetAttribute(s_mma_kernel, cudaFuncAttributeMaxDynamicSharedMemorySize, 65536);

    convert_w_kernel<<<dim3(H, 3), 256>>>(Wq, Wk, Wv);
    qkv_mma_kernel<<<BN / 64, 256, 2 * QKV_BUFSZ>>>(x, bq, bk, bv);
    s_mma_kernel<<<dim3(NPAIR2, B), 512, 65536>>>();
    ep_kernel<<<BN / 4, 256>>>();
    av_mma_kernel<<<dim3(72, B), 512>>>();
    reduce_kernel<<<(BN * H + 255) / 256, 256>>>(out);
}